// round 1
// baseline (speedup 1.0000x reference)
#include <cuda_runtime.h>
#include <math.h>

#define N_TOKEN 256
#define CP 128
#define C 32
#define H 4
#define NN (N_TOKEN * N_TOKEN)

// Scratch (allocation-free: __device__ globals)
__device__ float g_pn[NN * CP];   // layernormed pair
__device__ float g_q [NN * CP];   // [i,j,h*32+c]
__device__ float g_k [NN * CP];
__device__ float g_v [NN * CP];
__device__ float g_g [NN * CP];   // sigmoid gate
__device__ float g_b [NN * H];    // [j,k,h]
__device__ float g_o [NN * CP];   // gated attention output

// ---------------------------------------------------------------- LayerNorm
__global__ void k_ln(const float* __restrict__ pair,
                     const float* __restrict__ gamma,
                     const float* __restrict__ beta)
{
    const int row = blockIdx.x;
    const int t   = threadIdx.x;   // 0..127
    float x = pair[row * CP + t];

    __shared__ float sred[4];
    float s = x;
    #pragma unroll
    for (int off = 16; off; off >>= 1) s += __shfl_xor_sync(0xffffffffu, s, off);
    if ((t & 31) == 0) sred[t >> 5] = s;
    __syncthreads();
    float mu = (sred[0] + sred[1] + sred[2] + sred[3]) * (1.0f / CP);
    __syncthreads();

    float d  = x - mu;
    float sq = d * d;
    #pragma unroll
    for (int off = 16; off; off >>= 1) sq += __shfl_xor_sync(0xffffffffu, sq, off);
    if ((t & 31) == 0) sred[t >> 5] = sq;
    __syncthreads();
    float var = (sred[0] + sred[1] + sred[2] + sred[3]) * (1.0f / CP);

    g_pn[row * CP + t] = d * rsqrtf(var + 1e-5f) * gamma[t] + beta[t];
}

// ------------------------------------------------- q/k/v/g projection GEMM
// A = g_pn [65536,128], B = one of four [128,128] weights.
// grid.x = 8 (matrix*2 + n-half), grid.y = 1024 (m tiles of 64). 256 threads.
__global__ void k_proj(const float* __restrict__ Wq, const float* __restrict__ Wk,
                       const float* __restrict__ Wv, const float* __restrict__ Wg)
{
    const int nt  = blockIdx.x;
    const int mat = nt >> 1;
    const int n0  = (nt & 1) * 64;
    const int m0  = blockIdx.y * 64;
    const float* __restrict__ B = (mat == 0) ? Wq : (mat == 1) ? Wk : (mat == 2) ? Wv : Wg;

    __shared__ __align__(16) float As[64][68];  // [k][m], padded for alignment
    __shared__ __align__(16) float Bs[64][64];  // [k][n]

    const int tid = threadIdx.x;
    const int tx = tid & 15, ty = tid >> 4;

    float acc[4][4];
    #pragma unroll
    for (int i = 0; i < 4; i++)
        #pragma unroll
        for (int j = 0; j < 4; j++) acc[i][j] = 0.f;

    for (int kt = 0; kt < 2; ++kt) {
        const int k0 = kt * 64;
        #pragma unroll
        for (int it = 0; it < 4; ++it) {
            int idx = tid + it * 256;          // float4 index 0..1023
            int r   = idx >> 4;                // row 0..63
            int kk  = (idx & 15) << 2;         // col 0..60
            float4 a = *(const float4*)&g_pn[(m0 + r) * CP + k0 + kk];
            As[kk + 0][r] = a.x; As[kk + 1][r] = a.y;
            As[kk + 2][r] = a.z; As[kk + 3][r] = a.w;
        }
        #pragma unroll
        for (int it = 0; it < 4; ++it) {
            int idx = tid + it * 256;
            int kk  = idx >> 4;
            int n   = (idx & 15) << 2;
            *(float4*)&Bs[kk][n] = *(const float4*)&B[(k0 + kk) * CP + n0 + n];
        }
        __syncthreads();
        #pragma unroll
        for (int kk = 0; kk < 64; ++kk) {
            float4 a = *(const float4*)&As[kk][ty << 2];
            float4 b = *(const float4*)&Bs[kk][tx << 2];
            float av[4] = {a.x, a.y, a.z, a.w};
            float bv[4] = {b.x, b.y, b.z, b.w};
            #pragma unroll
            for (int i = 0; i < 4; i++)
                #pragma unroll
                for (int j = 0; j < 4; j++) acc[i][j] += av[i] * bv[j];
        }
        __syncthreads();
    }

    float* O = (mat == 0) ? g_q : (mat == 1) ? g_k : (mat == 2) ? g_v : g_g;
    #pragma unroll
    for (int i = 0; i < 4; i++) {
        int row = m0 + (ty << 2) + i;
        #pragma unroll
        for (int j = 0; j < 4; j++) {
            float vv = acc[i][j];
            if (mat == 3) vv = 1.f / (1.f + __expf(-vv));   // fused sigmoid
            O[row * CP + n0 + (tx << 2) + j] = vv;
        }
    }
}

// ---------------------------------------------------------------- bias GEMV
// g_b[row,4] = g_pn[row,:] @ Wb[128,4]. One warp per row.
__global__ void k_bias(const float* __restrict__ Wb)
{
    const int warp = (blockIdx.x * blockDim.x + threadIdx.x) >> 5;
    const int lane = threadIdx.x & 31;
    if (warp >= NN) return;
    float x0 = g_pn[warp * CP + lane];
    float x1 = g_pn[warp * CP + 32 + lane];
    float x2 = g_pn[warp * CP + 64 + lane];
    float x3 = g_pn[warp * CP + 96 + lane];
    #pragma unroll
    for (int o = 0; o < 4; ++o) {
        float p = x0 * Wb[lane * 4 + o] + x1 * Wb[(lane + 32) * 4 + o]
                + x2 * Wb[(lane + 64) * 4 + o] + x3 * Wb[(lane + 96) * 4 + o];
        #pragma unroll
        for (int off = 16; off; off >>= 1) p += __shfl_xor_sync(0xffffffffu, p, off);
        if (lane == 0) g_b[warp * 4 + o] = p;
    }
}

// --------------------------------------------------------------- attention
// grid: (jtile=8, h=4, i=256). 256 threads. K/V for (i,h) staged in smem.
__global__ void k_attn()
{
    extern __shared__ float sm[];
    float* ks  = sm;                  // 256*33
    float* vs  = ks + 256 * 33;       // 256*33
    float* qs  = vs + 256 * 33;       // 32
    float* att = qs + 32;             // 256
    float* red = att + 256;           // 8*32
    float* rsc = red + 256;           // 16

    const int jt = blockIdx.x, h = blockIdx.y, i = blockIdx.z;
    const int t  = threadIdx.x;       // 0..255
    const float scale = 0.17677669529663687f;  // 1/sqrt(32)

    // stage K and V for this (i,h)
    for (int idx = t; idx < 256 * 8; idx += 256) {
        int kk = idx >> 3, c4 = (idx & 7) << 2;
        const float4 kv = *(const float4*)&g_k[(i * 256 + kk) * CP + h * 32 + c4];
        ks[kk * 33 + c4 + 0] = kv.x; ks[kk * 33 + c4 + 1] = kv.y;
        ks[kk * 33 + c4 + 2] = kv.z; ks[kk * 33 + c4 + 3] = kv.w;
        const float4 vv = *(const float4*)&g_v[(i * 256 + kk) * CP + h * 32 + c4];
        vs[kk * 33 + c4 + 0] = vv.x; vs[kk * 33 + c4 + 1] = vv.y;
        vs[kk * 33 + c4 + 2] = vv.z; vs[kk * 33 + c4 + 3] = vv.w;
    }
    __syncthreads();

    for (int jj = 0; jj < 32; ++jj) {
        const int j = jt * 32 + jj;
        if (t < 32) qs[t] = g_q[(i * 256 + j) * CP + h * 32 + t];
        __syncthreads();

        // logit for k = t
        float acc = 0.f;
        const float* krow = &ks[t * 33];
        #pragma unroll
        for (int c = 0; c < 32; ++c) acc += qs[c] * krow[c];
        float logit = acc * scale + g_b[(j * 256 + t) * 4 + h];

        // block max
        float m = logit;
        #pragma unroll
        for (int off = 16; off; off >>= 1) m = fmaxf(m, __shfl_xor_sync(0xffffffffu, m, off));
        if ((t & 31) == 0) rsc[t >> 5] = m;
        __syncthreads();
        float bmax = rsc[0];
        #pragma unroll
        for (int w = 1; w < 8; ++w) bmax = fmaxf(bmax, rsc[w]);

        float e = __expf(logit - bmax);
        att[t] = e;
        float s = e;
        #pragma unroll
        for (int off = 16; off; off >>= 1) s += __shfl_xor_sync(0xffffffffu, s, off);
        if ((t & 31) == 0) rsc[8 + (t >> 5)] = s;
        __syncthreads();
        float bsum = rsc[8];
        #pragma unroll
        for (int w = 1; w < 8; ++w) bsum += rsc[8 + w];
        const float inv = 1.f / bsum;

        // AV: c = t&31, 8 k-groups of 32
        const int c = t & 31, grp = t >> 5;
        float p = 0.f;
        #pragma unroll
        for (int u = 0; u < 32; ++u) {
            int kk = grp * 32 + u;
            p += att[kk] * vs[kk * 33 + c];
        }
        red[grp * 32 + c] = p;
        __syncthreads();
        if (t < 32) {
            float o = 0.f;
            #pragma unroll
            for (int w = 0; w < 8; ++w) o += red[w * 32 + t];
            o *= inv;
            o *= g_g[(i * 256 + j) * CP + h * 32 + t];   // fused gate
            g_o[(i * 256 + j) * CP + h * 32 + t] = o;
        }
        __syncthreads();
    }
}

// -------------------------------------------------------- output projection
// out = g_o [65536,128] @ Wout [128,128]. grid (2, 1024), 256 threads.
__global__ void k_out(const float* __restrict__ Wout, float* __restrict__ out)
{
    const int n0 = blockIdx.x * 64;
    const int m0 = blockIdx.y * 64;

    __shared__ __align__(16) float As[64][68];
    __shared__ __align__(16) float Bs[64][64];

    const int tid = threadIdx.x;
    const int tx = tid & 15, ty = tid >> 4;

    float acc[4][4];
    #pragma unroll
    for (int i = 0; i < 4; i++)
        #pragma unroll
        for (int j = 0; j < 4; j++) acc[i][j] = 0.f;

    for (int kt = 0; kt < 2; ++kt) {
        const int k0 = kt * 64;
        #pragma unroll
        for (int it = 0; it < 4; ++it) {
            int idx = tid + it * 256;
            int r   = idx >> 4;
            int kk  = (idx & 15) << 2;
            float4 a = *(const float4*)&g_o[(m0 + r) * CP + k0 + kk];
            As[kk + 0][r] = a.x; As[kk + 1][r] = a.y;
            As[kk + 2][r] = a.z; As[kk + 3][r] = a.w;
        }
        #pragma unroll
        for (int it = 0; it < 4; ++it) {
            int idx = tid + it * 256;
            int kk  = idx >> 4;
            int n   = (idx & 15) << 2;
            *(float4*)&Bs[kk][n] = *(const float4*)&Wout[(k0 + kk) * CP + n0 + n];
        }
        __syncthreads();
        #pragma unroll
        for (int kk = 0; kk < 64; ++kk) {
            float4 a = *(const float4*)&As[kk][ty << 2];
            float4 b = *(const float4*)&Bs[kk][tx << 2];
            float av[4] = {a.x, a.y, a.z, a.w};
            float bv[4] = {b.x, b.y, b.z, b.w};
            #pragma unroll
            for (int i = 0; i < 4; i++)
                #pragma unroll
                for (int j = 0; j < 4; j++) acc[i][j] += av[i] * bv[j];
        }
        __syncthreads();
    }

    #pragma unroll
    for (int i = 0; i < 4; i++) {
        int row = m0 + (ty << 2) + i;
        #pragma unroll
        for (int j = 0; j < 4; j++)
            out[row * CP + n0 + (tx << 2) + j] = acc[i][j];
    }
}

// ----------------------------------------------------------------- launcher
extern "C" void kernel_launch(void* const* d_in, const int* in_sizes, int n_in,
                              void* d_out, int out_size)
{
    const float* pair  = (const float*)d_in[0];
    const float* gamma = (const float*)d_in[1];
    const float* beta  = (const float*)d_in[2];
    const float* Wq    = (const float*)d_in[3];
    const float* Wk    = (const float*)d_in[4];
    const float* Wv    = (const float*)d_in[5];
    const float* Wb    = (const float*)d_in[6];
    const float* Wg    = (const float*)d_in[7];
    const float* Wout  = (const float*)d_in[8];
    float* out = (float*)d_out;

    static const int attn_smem = (256 * 33 * 2 + 32 + 256 + 256 + 16) * (int)sizeof(float);
    cudaFuncSetAttribute(k_attn, cudaFuncAttributeMaxDynamicSharedMemorySize, attn_smem);

    k_ln  <<<NN, 128>>>(pair, gamma, beta);
    k_proj<<<dim3(8, NN / 64), 256>>>(Wq, Wk, Wv, Wg);
    k_bias<<<NN / 8, 256>>>(Wb);
    k_attn<<<dim3(8, H, N_TOKEN), 256, attn_smem>>>();
    k_out <<<dim3(2, NN / 64), 256>>>(Wout, out);
}

// round 2
// speedup vs baseline: 1.8260x; 1.8260x over previous
#include <cuda_runtime.h>
#include <math.h>

#define N_TOKEN 256
#define CP 128
#define C 32
#define H 4
#define NN (N_TOKEN * N_TOKEN)

// Scratch (allocation-free: __device__ globals)
__device__ float g_pn[NN * CP];   // layernormed pair
__device__ float g_q [NN * CP];   // [i,j,h*32+c]
__device__ float g_k [NN * CP];
__device__ float g_v [NN * CP];
__device__ float g_g [NN * CP];   // sigmoid gate
__device__ float g_b [H * NN];    // [h][j*256+k]
__device__ float g_o [NN * CP];   // gated attention output

// ------------------------------------------------------------- f32x2 helpers
typedef unsigned long long u64;

__device__ __forceinline__ void ffma2(u64& d, u64 a, u64 b) {
    asm volatile("fma.rn.f32x2 %0, %1, %2, %0;" : "+l"(d) : "l"(a), "l"(b));
}
__device__ __forceinline__ u64 pack2(float lo, float hi) {
    u64 r; asm("mov.b64 %0, {%1, %2};" : "=l"(r) : "f"(lo), "f"(hi)); return r;
}
__device__ __forceinline__ float2 unpack2(u64 v) {
    float2 r; asm("mov.b64 {%0, %1}, %2;" : "=f"(r.x), "=f"(r.y) : "l"(v)); return r;
}
__device__ __forceinline__ unsigned smaddr(const void* p) {
    unsigned a;
    asm("{ .reg .u64 t; cvta.to.shared.u64 t, %1; cvt.u32.u64 %0, t; }"
        : "=r"(a) : "l"(p));
    return a;
}
__device__ __forceinline__ void lds_2x64(u64& lo, u64& hi, unsigned addr) {
    asm volatile("ld.shared.v2.u64 {%0, %1}, [%2];" : "=l"(lo), "=l"(hi) : "r"(addr));
}

// ---------------------------------------------------------------- LayerNorm
__global__ void k_ln(const float* __restrict__ pair,
                     const float* __restrict__ gamma,
                     const float* __restrict__ beta)
{
    const int row = blockIdx.x;
    const int t   = threadIdx.x;   // 0..127
    float x = pair[row * CP + t];

    __shared__ float sred[4];
    float s = x;
    #pragma unroll
    for (int off = 16; off; off >>= 1) s += __shfl_xor_sync(0xffffffffu, s, off);
    if ((t & 31) == 0) sred[t >> 5] = s;
    __syncthreads();
    float mu = (sred[0] + sred[1] + sred[2] + sred[3]) * (1.0f / CP);
    __syncthreads();

    float d  = x - mu;
    float sq = d * d;
    #pragma unroll
    for (int off = 16; off; off >>= 1) sq += __shfl_xor_sync(0xffffffffu, sq, off);
    if ((t & 31) == 0) sred[t >> 5] = sq;
    __syncthreads();
    float var = (sred[0] + sred[1] + sred[2] + sred[3]) * (1.0f / CP);

    g_pn[row * CP + t] = d * rsqrtf(var + 1e-5f) * gamma[t] + beta[t];
}

// ------------------------------------------------- q/k/v/g projection GEMM
__global__ void __launch_bounds__(256) k_proj(
    const float* __restrict__ Wq, const float* __restrict__ Wk,
    const float* __restrict__ Wv, const float* __restrict__ Wg)
{
    const int nt  = blockIdx.x;
    const int mat = nt >> 1;
    const int n0  = (nt & 1) * 64;
    const int m0  = blockIdx.y * 64;
    const float* __restrict__ B = (mat == 0) ? Wq : (mat == 1) ? Wk : (mat == 2) ? Wv : Wg;

    __shared__ __align__(16) float As[64][68];  // [k][m]
    __shared__ __align__(16) float Bs[64][64];  // [k][n]

    const int tid = threadIdx.x;
    const int tx = tid & 15, ty = tid >> 4;

    u64 acc2[4][2];
    #pragma unroll
    for (int i = 0; i < 4; i++) { acc2[i][0] = 0ull; acc2[i][1] = 0ull; }

    for (int kt = 0; kt < 2; ++kt) {
        const int k0 = kt * 64;
        #pragma unroll
        for (int it = 0; it < 4; ++it) {
            int idx = tid + it * 256;
            int r   = idx >> 4;
            int kk  = (idx & 15) << 2;
            float4 a = *(const float4*)&g_pn[(m0 + r) * CP + k0 + kk];
            As[kk + 0][r] = a.x; As[kk + 1][r] = a.y;
            As[kk + 2][r] = a.z; As[kk + 3][r] = a.w;
        }
        #pragma unroll
        for (int it = 0; it < 4; ++it) {
            int idx = tid + it * 256;
            int kk  = idx >> 4;
            int n   = (idx & 15) << 2;
            *(float4*)&Bs[kk][n] = *(const float4*)&B[(k0 + kk) * CP + n0 + n];
        }
        __syncthreads();
        #pragma unroll
        for (int kk = 0; kk < 64; ++kk) {
            float4 a = *(const float4*)&As[kk][ty << 2];
            u64 b01, b23;
            lds_2x64(b01, b23, smaddr(&Bs[kk][tx << 2]));
            float av[4] = {a.x, a.y, a.z, a.w};
            #pragma unroll
            for (int i = 0; i < 4; i++) {
                u64 aa = pack2(av[i], av[i]);
                ffma2(acc2[i][0], aa, b01);
                ffma2(acc2[i][1], aa, b23);
            }
        }
        __syncthreads();
    }

    float* O = (mat == 0) ? g_q : (mat == 1) ? g_k : (mat == 2) ? g_v : g_g;
    #pragma unroll
    for (int i = 0; i < 4; i++) {
        int row = m0 + (ty << 2) + i;
        #pragma unroll
        for (int p = 0; p < 2; p++) {
            float2 vv = unpack2(acc2[i][p]);
            float v0 = vv.x, v1 = vv.y;
            if (mat == 3) {
                v0 = 1.f / (1.f + __expf(-v0));
                v1 = 1.f / (1.f + __expf(-v1));
            }
            O[row * CP + n0 + (tx << 2) + 2 * p + 0] = v0;
            O[row * CP + n0 + (tx << 2) + 2 * p + 1] = v1;
        }
    }
}

// ---------------------------------------------------------------- bias GEMV
// g_b[h][row] = g_pn[row,:] @ Wb[:,h]
__global__ void k_bias(const float* __restrict__ Wb)
{
    const int warp = (blockIdx.x * blockDim.x + threadIdx.x) >> 5;
    const int lane = threadIdx.x & 31;
    if (warp >= NN) return;
    float x0 = g_pn[warp * CP + lane];
    float x1 = g_pn[warp * CP + 32 + lane];
    float x2 = g_pn[warp * CP + 64 + lane];
    float x3 = g_pn[warp * CP + 96 + lane];
    #pragma unroll
    for (int o = 0; o < 4; ++o) {
        float p = x0 * Wb[lane * 4 + o] + x1 * Wb[(lane + 32) * 4 + o]
                + x2 * Wb[(lane + 64) * 4 + o] + x3 * Wb[(lane + 96) * 4 + o];
        #pragma unroll
        for (int off = 16; off; off >>= 1) p += __shfl_xor_sync(0xffffffffu, p, off);
        if (lane == 0) g_b[o * NN + warp] = p;
    }
}

// --------------------------------------------------------------- attention
// One block per (i, h). 256 threads = 8 warps. K/Vt staged once; 4 j-tiles
// of 64. Warp w owns j rows w*8..w*8+7 -> softmax is warp-local.
#define KS_STRIDE 36
#define VT_STRIDE 260
#define QS_STRIDE 36
#define AS_STRIDE 260
#define ATTN_SMEM ((256 * KS_STRIDE + 32 * VT_STRIDE + 64 * QS_STRIDE + 64 * AS_STRIDE) * 4)

__global__ void __launch_bounds__(256, 1) k_attn()
{
    extern __shared__ float sm[];
    float* Ks = sm;                            // [256][36]
    float* Vt = Ks + 256 * KS_STRIDE;          // [32][260]  (transposed V)
    float* Qs = Vt + 32 * VT_STRIDE;           // [64][36]
    float* Az = Qs + 64 * QS_STRIDE;           // [64][260]  bias tile, then exp tile

    const int i = blockIdx.x, h = blockIdx.y;
    const int t = threadIdx.x;
    const int w = t >> 5, lane = t & 31;
    const int jbase = w * 8;
    const float scale = 0.17677669529663687f;  // 1/sqrt(32)

    const float* gk = g_k + (size_t)(i * 256) * CP + h * 32;
    const float* gv = g_v + (size_t)(i * 256) * CP + h * 32;
    const float* gq = g_q + (size_t)(i * 256) * CP + h * 32;
    const float* gg = g_g + (size_t)(i * 256) * CP + h * 32;
    const float* gb = g_b + (size_t)h * NN;

    // stage K (row-major, pad 36) and V transposed (pad 260)
    for (int idx = t; idx < 256 * 32; idx += 256) {
        int kk = idx >> 5, c = idx & 31;
        float kvk = gk[kk * CP + c];
        float kvv = gv[kk * CP + c];
        Ks[kk * KS_STRIDE + c] = kvk;
        Vt[c * VT_STRIDE + kk] = kvv;
    }
    __syncthreads();

    const unsigned ks_base = smaddr(Ks);
    const unsigned qs_base = smaddr(Qs);
    const unsigned as_base = smaddr(Az);
    const unsigned vt_base = smaddr(Vt);

    for (int jt = 0; jt < 4; ++jt) {
        const int j0 = jt * 64;

        // load Q tile and bias tile
        for (int idx = t; idx < 64 * 32; idx += 256) {
            int r = idx >> 5, c = idx & 31;
            Qs[r * QS_STRIDE + c] = gq[(j0 + r) * CP + c];
        }
        #pragma unroll
        for (int it = 0; it < 16; ++it) {
            int idx = t + it * 256;                 // 4096 float4 slots
            int r  = idx >> 6;
            int c4 = (idx & 63) << 2;
            float4 b4 = *(const float4*)&gb[(j0 + r) * 256 + c4];
            *(float4*)&Az[r * AS_STRIDE + c4] = b4;
        }
        __syncthreads();

        // ---- logits: acc[jj][u] over c, f32x2-packed along c ----
        u64 acc2[8][8];
        #pragma unroll
        for (int jj = 0; jj < 8; ++jj)
            #pragma unroll
            for (int u = 0; u < 8; ++u) acc2[jj][u] = 0ull;

        #pragma unroll
        for (int c4 = 0; c4 < 32; c4 += 4) {
            u64 k_lo[8], k_hi[8];
            #pragma unroll
            for (int u = 0; u < 8; ++u)
                lds_2x64(k_lo[u], k_hi[u],
                         ks_base + ((lane + 32 * u) * KS_STRIDE + c4) * 4);
            #pragma unroll
            for (int jj = 0; jj < 8; ++jj) {
                u64 q_lo, q_hi;
                lds_2x64(q_lo, q_hi,
                         qs_base + ((jbase + jj) * QS_STRIDE + c4) * 4);
                #pragma unroll
                for (int u = 0; u < 8; ++u) {
                    ffma2(acc2[jj][u], q_lo, k_lo[u]);
                    ffma2(acc2[jj][u], q_hi, k_hi[u]);
                }
            }
        }

        // ---- softmax (warp-local) + write exp back into Az ----
        float inv[8];
        #pragma unroll
        for (int jj = 0; jj < 8; ++jj) {
            const int jr = jbase + jj;
            float lg[8];
            #pragma unroll
            for (int u = 0; u < 8; ++u) {
                float2 p = unpack2(acc2[jj][u]);
                lg[u] = (p.x + p.y) * scale + Az[jr * AS_STRIDE + lane + 32 * u];
            }
            float m = lg[0];
            #pragma unroll
            for (int u = 1; u < 8; ++u) m = fmaxf(m, lg[u]);
            #pragma unroll
            for (int off = 16; off; off >>= 1)
                m = fmaxf(m, __shfl_xor_sync(0xffffffffu, m, off));
            float s = 0.f;
            #pragma unroll
            for (int u = 0; u < 8; ++u) {
                float e = __expf(lg[u] - m);
                Az[jr * AS_STRIDE + lane + 32 * u] = e;
                s += e;
            }
            #pragma unroll
            for (int off = 16; off; off >>= 1)
                s += __shfl_xor_sync(0xffffffffu, s, off);
            inv[jj] = 1.f / s;
        }
        __syncthreads();

        // ---- AV: o[j][c], lane = c, f32x2-packed along k ----
        u64 o2[8];
        #pragma unroll
        for (int jj = 0; jj < 8; ++jj) o2[jj] = 0ull;

        #pragma unroll 4
        for (int k4 = 0; k4 < 256; k4 += 4) {
            u64 v_lo, v_hi;
            lds_2x64(v_lo, v_hi, vt_base + (lane * VT_STRIDE + k4) * 4);
            #pragma unroll
            for (int jj = 0; jj < 8; ++jj) {
                u64 a_lo, a_hi;
                lds_2x64(a_lo, a_hi, as_base + ((jbase + jj) * AS_STRIDE + k4) * 4);
                ffma2(o2[jj], a_lo, v_lo);
                ffma2(o2[jj], a_hi, v_hi);
            }
        }

        #pragma unroll
        for (int jj = 0; jj < 8; ++jj) {
            float2 p = unpack2(o2[jj]);
            const int j = j0 + jbase + jj;
            float o = (p.x + p.y) * inv[jj];
            o *= gg[j * CP + lane];
            g_o[(size_t)(i * 256 + j) * CP + h * 32 + lane] = o;
        }
        __syncthreads();
    }
}

// -------------------------------------------------------- output projection
__global__ void __launch_bounds__(256) k_out(const float* __restrict__ Wout,
                                             float* __restrict__ out)
{
    const int n0 = blockIdx.x * 64;
    const int m0 = blockIdx.y * 64;

    __shared__ __align__(16) float As[64][68];
    __shared__ __align__(16) float Bs[64][64];

    const int tid = threadIdx.x;
    const int tx = tid & 15, ty = tid >> 4;

    u64 acc2[4][2];
    #pragma unroll
    for (int i = 0; i < 4; i++) { acc2[i][0] = 0ull; acc2[i][1] = 0ull; }

    for (int kt = 0; kt < 2; ++kt) {
        const int k0 = kt * 64;
        #pragma unroll
        for (int it = 0; it < 4; ++it) {
            int idx = tid + it * 256;
            int r   = idx >> 4;
            int kk  = (idx & 15) << 2;
            float4 a = *(const float4*)&g_o[(size_t)(m0 + r) * CP + k0 + kk];
            As[kk + 0][r] = a.x; As[kk + 1][r] = a.y;
            As[kk + 2][r] = a.z; As[kk + 3][r] = a.w;
        }
        #pragma unroll
        for (int it = 0; it < 4; ++it) {
            int idx = tid + it * 256;
            int kk  = idx >> 4;
            int n   = (idx & 15) << 2;
            *(float4*)&Bs[kk][n] = *(const float4*)&Wout[(k0 + kk) * CP + n0 + n];
        }
        __syncthreads();
        #pragma unroll
        for (int kk = 0; kk < 64; ++kk) {
            float4 a = *(const float4*)&As[kk][ty << 2];
            u64 b01, b23;
            lds_2x64(b01, b23, smaddr(&Bs[kk][tx << 2]));
            float av[4] = {a.x, a.y, a.z, a.w};
            #pragma unroll
            for (int i = 0; i < 4; i++) {
                u64 aa = pack2(av[i], av[i]);
                ffma2(acc2[i][0], aa, b01);
                ffma2(acc2[i][1], aa, b23);
            }
        }
        __syncthreads();
    }

    #pragma unroll
    for (int i = 0; i < 4; i++) {
        int row = m0 + (ty << 2) + i;
        #pragma unroll
        for (int p = 0; p < 2; p++) {
            float2 vv = unpack2(acc2[i][p]);
            out[(size_t)row * CP + n0 + (tx << 2) + 2 * p + 0] = vv.x;
            out[(size_t)row * CP + n0 + (tx << 2) + 2 * p + 1] = vv.y;
        }
    }
}

// ----------------------------------------------------------------- launcher
extern "C" void kernel_launch(void* const* d_in, const int* in_sizes, int n_in,
                              void* d_out, int out_size)
{
    const float* pair  = (const float*)d_in[0];
    const float* gamma = (const float*)d_in[1];
    const float* beta  = (const float*)d_in[2];
    const float* Wq    = (const float*)d_in[3];
    const float* Wk    = (const float*)d_in[4];
    const float* Wv    = (const float*)d_in[5];
    const float* Wb    = (const float*)d_in[6];
    const float* Wg    = (const float*)d_in[7];
    const float* Wout  = (const float*)d_in[8];
    float* out = (float*)d_out;

    cudaFuncSetAttribute(k_attn, cudaFuncAttributeMaxDynamicSharedMemorySize, ATTN_SMEM);

    k_ln  <<<NN, 128>>>(pair, gamma, beta);
    k_proj<<<dim3(8, NN / 64), 256>>>(Wq, Wk, Wv, Wg);
    k_bias<<<NN / 8, 256>>>(Wb);
    k_attn<<<dim3(N_TOKEN, H), 256, ATTN_SMEM>>>();
    k_out <<<dim3(2, NN / 64), 256>>>(Wout, out);
}

// round 4
// speedup vs baseline: 2.9184x; 1.5983x over previous
#include <cuda_runtime.h>
#include <math.h>
#include <cstdint>

#define N_TOKEN 256
#define CP 128
#define H 4
#define NN (N_TOKEN * N_TOKEN)

// Scratch (allocation-free: __device__ globals)
__device__ float g_pn[NN * CP];   // layernormed pair
__device__ float g_q [NN * CP];   // [i,j,h*32+c]
__device__ float g_k [NN * CP];
__device__ float g_v [NN * CP];
__device__ float g_g [NN * CP];   // sigmoid gate
__device__ float g_b [H * NN];    // [h][j*256+k]
__device__ float g_o [NN * CP];   // gated attention output

// ------------------------------------------------------------- f32x2 helpers
typedef unsigned long long u64;

__device__ __forceinline__ void ffma2(u64& d, u64 a, u64 b) {
    asm volatile("fma.rn.f32x2 %0, %1, %2, %0;" : "+l"(d) : "l"(a), "l"(b));
}
__device__ __forceinline__ float2 unpack2(u64 v) {
    float2 r; asm("mov.b64 {%0, %1}, %2;" : "=f"(r.x), "=f"(r.y) : "l"(v)); return r;
}
__device__ __forceinline__ unsigned smaddr(const void* p) {
    unsigned a;
    asm("{ .reg .u64 t; cvta.to.shared.u64 t, %1; cvt.u32.u64 %0, t; }"
        : "=r"(a) : "l"(p));
    return a;
}
__device__ __forceinline__ void lds_2x64(u64& lo, u64& hi, unsigned addr) {
    asm volatile("ld.shared.v2.u64 {%0, %1}, [%2];" : "=l"(lo), "=l"(hi) : "r"(addr));
}

// --------------------------------------------------------------- mma helpers
__device__ __forceinline__ uint32_t f2tf32(float f) {
    uint32_t u; asm("cvt.rna.tf32.f32 %0, %1;" : "=r"(u) : "f"(f)); return u;
}
__device__ __forceinline__ void mma_tf32(float c[4],
                                         uint32_t a0, uint32_t a1,
                                         uint32_t a2, uint32_t a3,
                                         uint32_t b0, uint32_t b1) {
    asm volatile(
        "mma.sync.aligned.m16n8k8.row.col.f32.tf32.tf32.f32 "
        "{%0,%1,%2,%3}, {%4,%5,%6,%7}, {%8,%9}, {%0,%1,%2,%3};"
        : "+f"(c[0]), "+f"(c[1]), "+f"(c[2]), "+f"(c[3])
        : "r"(a0), "r"(a1), "r"(a2), "r"(a3), "r"(b0), "r"(b1));
}

// --------------------------------------------------- LayerNorm + bias (fused)
__global__ void k_ln(const float* __restrict__ pair,
                     const float* __restrict__ gamma,
                     const float* __restrict__ beta,
                     const float* __restrict__ Wb)
{
    const int row = blockIdx.x;
    const int t   = threadIdx.x;   // 0..127
    float x = pair[row * CP + t];

    __shared__ float sred[4];
    __shared__ float sbias[4][4];  // [warp][h]
    float s = x;
    #pragma unroll
    for (int off = 16; off; off >>= 1) s += __shfl_xor_sync(0xffffffffu, s, off);
    if ((t & 31) == 0) sred[t >> 5] = s;
    __syncthreads();
    float mu = (sred[0] + sred[1] + sred[2] + sred[3]) * (1.0f / CP);
    __syncthreads();

    float d  = x - mu;
    float sq = d * d;
    #pragma unroll
    for (int off = 16; off; off >>= 1) sq += __shfl_xor_sync(0xffffffffu, sq, off);
    if ((t & 31) == 0) sred[t >> 5] = sq;
    __syncthreads();
    float var = (sred[0] + sred[1] + sred[2] + sred[3]) * (1.0f / CP);

    float pn = d * rsqrtf(var + 1e-5f) * gamma[t] + beta[t];
    g_pn[row * CP + t] = pn;

    // fused bias projection: g_b[h][row] = sum_t pn[t] * Wb[t][h]
    float pb[4];
    #pragma unroll
    for (int h = 0; h < 4; ++h) pb[h] = pn * Wb[t * 4 + h];
    #pragma unroll
    for (int h = 0; h < 4; ++h) {
        #pragma unroll
        for (int off = 16; off; off >>= 1)
            pb[h] += __shfl_xor_sync(0xffffffffu, pb[h], off);
    }
    if ((t & 31) == 0) {
        #pragma unroll
        for (int h = 0; h < 4; ++h) sbias[t >> 5][h] = pb[h];
    }
    __syncthreads();
    if (t < 4)
        g_b[t * NN + row] = sbias[0][t] + sbias[1][t] + sbias[2][t] + sbias[3][t];
}

// ------------------------------------------- q/k/v/g projection (tf32 mma.sync)
// CTA: 128-row tile x 128 cols, 8 warps (warp_m = wid&1 -> 64 rows,
// warp_n = wid>>1 -> 32 cols). A staged once (tf32), 4 weight mats looped.
#define PA_STRIDE 132
#define PB_STRIDE 136
#define PJ_SMEM ((128 * PA_STRIDE + 128 * PB_STRIDE) * 4)

__global__ void __launch_bounds__(256, 1) k_proj_mma(
    const float* __restrict__ Wq, const float* __restrict__ Wk,
    const float* __restrict__ Wv, const float* __restrict__ Wg)
{
    extern __shared__ uint32_t usm[];
    uint32_t* As = usm;                       // [128][132] tf32
    uint32_t* Bs = usm + 128 * PA_STRIDE;     // [128][136] tf32 (k-major)

    const int tid = threadIdx.x;
    const int wid = tid >> 5, lane = tid & 31;
    const int warp_m = wid & 1, warp_n = wid >> 1;
    const int gid = lane >> 2, tig = lane & 3;  // groupID, thread-in-group
    const int m0 = blockIdx.x * 128;

    // stage A (tf32-converted)
    #pragma unroll
    for (int it = 0; it < 16; ++it) {
        int idx = tid + it * 256;
        int r = idx >> 5, c4 = (idx & 31) << 2;
        float4 v = *(const float4*)&g_pn[(size_t)(m0 + r) * CP + c4];
        uint4 u = make_uint4(f2tf32(v.x), f2tf32(v.y), f2tf32(v.z), f2tf32(v.w));
        *(uint4*)&As[r * PA_STRIDE + c4] = u;
    }

    const float* Ws[4] = {Wq, Wk, Wv, Wg};
    float* Os[4] = {g_q, g_k, g_v, g_g};

    #pragma unroll
    for (int mat = 0; mat < 4; ++mat) {
        // stage B (W is [k][n] row-major in gmem, same layout in smem)
        #pragma unroll
        for (int it = 0; it < 16; ++it) {
            int idx = tid + it * 256;
            int k = idx >> 5, n4 = (idx & 31) << 2;
            float4 v = *(const float4*)&Ws[mat][(size_t)k * CP + n4];
            uint4 u = make_uint4(f2tf32(v.x), f2tf32(v.y), f2tf32(v.z), f2tf32(v.w));
            *(uint4*)&Bs[k * PB_STRIDE + n4] = u;
        }
        __syncthreads();

        float c[4][4][4];
        #pragma unroll
        for (int mf = 0; mf < 4; ++mf)
            #pragma unroll
            for (int nf = 0; nf < 4; ++nf)
                #pragma unroll
                for (int q = 0; q < 4; ++q) c[mf][nf][q] = 0.f;

        #pragma unroll
        for (int ks = 0; ks < 16; ++ks) {
            const int k0 = ks * 8;
            uint32_t a[4][4], b[4][2];
            #pragma unroll
            for (int mf = 0; mf < 4; ++mf) {
                int r = warp_m * 64 + mf * 16 + gid;
                a[mf][0] = As[r * PA_STRIDE + k0 + tig];
                a[mf][1] = As[(r + 8) * PA_STRIDE + k0 + tig];
                a[mf][2] = As[r * PA_STRIDE + k0 + tig + 4];
                a[mf][3] = As[(r + 8) * PA_STRIDE + k0 + tig + 4];
            }
            #pragma unroll
            for (int nf = 0; nf < 4; ++nf) {
                int n = warp_n * 32 + nf * 8 + gid;
                b[nf][0] = Bs[(k0 + tig) * PB_STRIDE + n];
                b[nf][1] = Bs[(k0 + tig + 4) * PB_STRIDE + n];
            }
            #pragma unroll
            for (int mf = 0; mf < 4; ++mf)
                #pragma unroll
                for (int nf = 0; nf < 4; ++nf)
                    mma_tf32(c[mf][nf], a[mf][0], a[mf][1], a[mf][2], a[mf][3],
                             b[nf][0], b[nf][1]);
        }
        __syncthreads();   // Bs free for next mat

        float* O = Os[mat];
        #pragma unroll
        for (int mf = 0; mf < 4; ++mf) {
            #pragma unroll
            for (int nf = 0; nf < 4; ++nf) {
                int r  = m0 + warp_m * 64 + mf * 16 + gid;
                int cb = warp_n * 32 + nf * 8 + 2 * tig;
                float v0 = c[mf][nf][0], v1 = c[mf][nf][1];
                float v2 = c[mf][nf][2], v3 = c[mf][nf][3];
                if (mat == 3) {
                    v0 = 1.f / (1.f + __expf(-v0));
                    v1 = 1.f / (1.f + __expf(-v1));
                    v2 = 1.f / (1.f + __expf(-v2));
                    v3 = 1.f / (1.f + __expf(-v3));
                }
                *(float2*)&O[(size_t)r * CP + cb]       = make_float2(v0, v1);
                *(float2*)&O[(size_t)(r + 8) * CP + cb] = make_float2(v2, v3);
            }
        }
    }
}

// ----------------------------------------------- output projection (tf32 mma)
__global__ void __launch_bounds__(256, 1) k_out_mma(const float* __restrict__ Wout,
                                                    float* __restrict__ out)
{
    extern __shared__ uint32_t usm[];
    uint32_t* As = usm;
    uint32_t* Bs = usm + 128 * PA_STRIDE;

    const int tid = threadIdx.x;
    const int wid = tid >> 5, lane = tid & 31;
    const int warp_m = wid & 1, warp_n = wid >> 1;
    const int gid = lane >> 2, tig = lane & 3;
    const int m0 = blockIdx.x * 128;

    #pragma unroll
    for (int it = 0; it < 16; ++it) {
        int idx = tid + it * 256;
        int r = idx >> 5, c4 = (idx & 31) << 2;
        float4 v = *(const float4*)&g_o[(size_t)(m0 + r) * CP + c4];
        uint4 u = make_uint4(f2tf32(v.x), f2tf32(v.y), f2tf32(v.z), f2tf32(v.w));
        *(uint4*)&As[r * PA_STRIDE + c4] = u;
    }
    #pragma unroll
    for (int it = 0; it < 16; ++it) {
        int idx = tid + it * 256;
        int k = idx >> 5, n4 = (idx & 31) << 2;
        float4 v = *(const float4*)&Wout[(size_t)k * CP + n4];
        uint4 u = make_uint4(f2tf32(v.x), f2tf32(v.y), f2tf32(v.z), f2tf32(v.w));
        *(uint4*)&Bs[k * PB_STRIDE + n4] = u;
    }
    __syncthreads();

    float c[4][4][4];
    #pragma unroll
    for (int mf = 0; mf < 4; ++mf)
        #pragma unroll
        for (int nf = 0; nf < 4; ++nf)
            #pragma unroll
            for (int q = 0; q < 4; ++q) c[mf][nf][q] = 0.f;

    #pragma unroll
    for (int ks = 0; ks < 16; ++ks) {
        const int k0 = ks * 8;
        uint32_t a[4][4], b[4][2];
        #pragma unroll
        for (int mf = 0; mf < 4; ++mf) {
            int r = warp_m * 64 + mf * 16 + gid;
            a[mf][0] = As[r * PA_STRIDE + k0 + tig];
            a[mf][1] = As[(r + 8) * PA_STRIDE + k0 + tig];
            a[mf][2] = As[r * PA_STRIDE + k0 + tig + 4];
            a[mf][3] = As[(r + 8) * PA_STRIDE + k0 + tig + 4];
        }
        #pragma unroll
        for (int nf = 0; nf < 4; ++nf) {
            int n = warp_n * 32 + nf * 8 + gid;
            b[nf][0] = Bs[(k0 + tig) * PB_STRIDE + n];
            b[nf][1] = Bs[(k0 + tig + 4) * PB_STRIDE + n];
        }
        #pragma unroll
        for (int mf = 0; mf < 4; ++mf)
            #pragma unroll
            for (int nf = 0; nf < 4; ++nf)
                mma_tf32(c[mf][nf], a[mf][0], a[mf][1], a[mf][2], a[mf][3],
                         b[nf][0], b[nf][1]);
    }

    #pragma unroll
    for (int mf = 0; mf < 4; ++mf) {
        #pragma unroll
        for (int nf = 0; nf < 4; ++nf) {
            int r  = m0 + warp_m * 64 + mf * 16 + gid;
            int cb = warp_n * 32 + nf * 8 + 2 * tig;
            *(float2*)&out[(size_t)r * CP + cb] =
                make_float2(c[mf][nf][0], c[mf][nf][1]);
            *(float2*)&out[(size_t)(r + 8) * CP + cb] =
                make_float2(c[mf][nf][2], c[mf][nf][3]);
        }
    }
}

// --------------------------------------------------------------- attention
// One block per (i, h). 256 threads = 8 warps. jtile=32 -> 2 CTAs/SM.
// Warp w owns j rows w*4..w*4+3 of each tile -> softmax warp-local.
#define KS_STRIDE 36
#define VT_STRIDE 260
#define QS_STRIDE 36
#define AS_STRIDE 260
#define ATTN_SMEM ((256 * KS_STRIDE + 32 * VT_STRIDE + 32 * QS_STRIDE + 32 * AS_STRIDE) * 4)

__global__ void __launch_bounds__(256, 2) k_attn()
{
    extern __shared__ float sm[];
    float* Ks = sm;                            // [256][36]
    float* Vt = Ks + 256 * KS_STRIDE;          // [32][260]  (transposed V)
    float* Qs = Vt + 32 * VT_STRIDE;           // [32][36]
    float* Az = Qs + 32 * QS_STRIDE;           // [32][260]  exp tile (warp-private rows)

    const int i = blockIdx.x, h = blockIdx.y;
    const int t = threadIdx.x;
    const int w = t >> 5, lane = t & 31;
    const int jbase = w * 4;
    const float scale = 0.17677669529663687f;  // 1/sqrt(32)

    const float* gk = g_k + (size_t)(i * 256) * CP + h * 32;
    const float* gv = g_v + (size_t)(i * 256) * CP + h * 32;
    const float* gq = g_q + (size_t)(i * 256) * CP + h * 32;
    const float* gg = g_g + (size_t)(i * 256) * CP + h * 32;
    const float* __restrict__ gb = g_b + (size_t)h * NN;

    for (int idx = t; idx < 256 * 32; idx += 256) {
        int kk = idx >> 5, c = idx & 31;
        Ks[kk * KS_STRIDE + c] = gk[kk * CP + c];
        Vt[c * VT_STRIDE + kk] = gv[kk * CP + c];
    }
    __syncthreads();

    const unsigned ks_base = smaddr(Ks);
    const unsigned qs_base = smaddr(Qs);
    const unsigned as_base = smaddr(Az);
    const unsigned vt_base = smaddr(Vt);

    for (int jt = 0; jt < 8; ++jt) {
        const int j0 = jt * 32;

        for (int idx = t; idx < 32 * 32; idx += 256) {
            int r = idx >> 5, c = idx & 31;
            Qs[r * QS_STRIDE + c] = gq[(j0 + r) * CP + c];
        }
        __syncthreads();

        // ---- logits: acc[jj][u] over c, f32x2-packed along c ----
        u64 acc2[4][8];
        #pragma unroll
        for (int jj = 0; jj < 4; ++jj)
            #pragma unroll
            for (int u = 0; u < 8; ++u) acc2[jj][u] = 0ull;

        #pragma unroll
        for (int c4 = 0; c4 < 32; c4 += 4) {
            u64 q_lo[4], q_hi[4];
            #pragma unroll
            for (int jj = 0; jj < 4; ++jj)
                lds_2x64(q_lo[jj], q_hi[jj],
                         qs_base + ((jbase + jj) * QS_STRIDE + c4) * 4);
            #pragma unroll
            for (int u = 0; u < 8; ++u) {
                u64 k_lo, k_hi;
                lds_2x64(k_lo, k_hi, ks_base + ((lane + 32 * u) * KS_STRIDE + c4) * 4);
                #pragma unroll
                for (int jj = 0; jj < 4; ++jj) {
                    ffma2(acc2[jj][u], q_lo[jj], k_lo);
                    ffma2(acc2[jj][u], q_hi[jj], k_hi);
                }
            }
        }

        // ---- softmax (warp-local), bias straight from L2, exp into Az ----
        float inv[4];
        #pragma unroll
        for (int jj = 0; jj < 4; ++jj) {
            const int jr = jbase + jj;            // tile-local row
            const int jglob = j0 + jr;            // global j
            float b8[8];
            #pragma unroll
            for (int u = 0; u < 8; ++u)
                b8[u] = __ldg(&gb[jglob * 256 + lane + 32 * u]);
            float lg[8];
            #pragma unroll
            for (int u = 0; u < 8; ++u) {
                float2 p = unpack2(acc2[jj][u]);
                lg[u] = (p.x + p.y) * scale + b8[u];
            }
            float m = lg[0];
            #pragma unroll
            for (int u = 1; u < 8; ++u) m = fmaxf(m, lg[u]);
            #pragma unroll
            for (int off = 16; off; off >>= 1)
                m = fmaxf(m, __shfl_xor_sync(0xffffffffu, m, off));
            float s = 0.f;
            #pragma unroll
            for (int u = 0; u < 8; ++u) {
                float e = __expf(lg[u] - m);
                Az[jr * AS_STRIDE + lane + 32 * u] = e;
                s += e;
            }
            #pragma unroll
            for (int off = 16; off; off >>= 1)
                s += __shfl_xor_sync(0xffffffffu, s, off);
            inv[jj] = 1.f / s;
        }
        // Az rows are warp-private: no block sync needed before AV.

        // ---- AV: o[j][c], lane = c, split accumulator chains ----
        u64 oa[4], ob[4];
        #pragma unroll
        for (int jj = 0; jj < 4; ++jj) { oa[jj] = 0ull; ob[jj] = 0ull; }

        #pragma unroll 4
        for (int k4 = 0; k4 < 256; k4 += 4) {
            u64 v_lo, v_hi;
            lds_2x64(v_lo, v_hi, vt_base + (lane * VT_STRIDE + k4) * 4);
            #pragma unroll
            for (int jj = 0; jj < 4; ++jj) {
                u64 a_lo, a_hi;
                lds_2x64(a_lo, a_hi, as_base + ((jbase + jj) * AS_STRIDE + k4) * 4);
                ffma2(oa[jj], a_lo, v_lo);
                ffma2(ob[jj], a_hi, v_hi);
            }
        }

        #pragma unroll
        for (int jj = 0; jj < 4; ++jj) {
            float2 pa = unpack2(oa[jj]);
            float2 pb = unpack2(ob[jj]);
            const int j = j0 + jbase + jj;
            float o = (pa.x + pa.y + pb.x + pb.y) * inv[jj];
            o *= gg[j * CP + lane];
            g_o[(size_t)(i * 256 + j) * CP + h * 32 + lane] = o;
        }
        __syncthreads();
    }
}

// ----------------------------------------------------------------- launcher
extern "C" void kernel_launch(void* const* d_in, const int* in_sizes, int n_in,
                              void* d_out, int out_size)
{
    const float* pair  = (const float*)d_in[0];
    const float* gamma = (const float*)d_in[1];
    const float* beta  = (const float*)d_in[2];
    const float* Wq    = (const float*)d_in[3];
    const float* Wk    = (const float*)d_in[4];
    const float* Wv    = (const float*)d_in[5];
    const float* Wb    = (const float*)d_in[6];
    const float* Wg    = (const float*)d_in[7];
    const float* Wout  = (const float*)d_in[8];
    float* out = (float*)d_out;

    cudaFuncSetAttribute(k_proj_mma, cudaFuncAttributeMaxDynamicSharedMemorySize, PJ_SMEM);
    cudaFuncSetAttribute(k_out_mma,  cudaFuncAttributeMaxDynamicSharedMemorySize, PJ_SMEM);
    cudaFuncSetAttribute(k_attn,     cudaFuncAttributeMaxDynamicSharedMemorySize, ATTN_SMEM);

    k_ln      <<<NN, 128>>>(pair, gamma, beta, Wb);
    k_proj_mma<<<NN / 128, 256, PJ_SMEM>>>(Wq, Wk, Wv, Wg);
    k_attn    <<<dim3(N_TOKEN, H), 256, ATTN_SMEM>>>();
    k_out_mma <<<NN / 128, 256, PJ_SMEM>>>(Wout, out);
}

// round 5
// speedup vs baseline: 3.0922x; 1.0595x over previous
#include <cuda_runtime.h>
#include <math.h>
#include <cstdint>

#define N_TOKEN 256
#define CP 128
#define H 4
#define NN (N_TOKEN * N_TOKEN)

// Scratch (allocation-free: __device__ globals)
__device__ float g_pn[NN * CP];   // layernormed pair
__device__ float g_q [NN * CP];   // [i,j,h*32+c]
__device__ float g_k [NN * CP];
__device__ float g_v [NN * CP];
__device__ float g_g [NN * CP];   // sigmoid gate
__device__ float g_b [H * NN];    // [h][j*256+k]
__device__ float g_o [NN * CP];   // gated attention output

// --------------------------------------------------------------- mma helpers
__device__ __forceinline__ uint32_t f2tf32(float f) {
    uint32_t u; asm("cvt.rna.tf32.f32 %0, %1;" : "=r"(u) : "f"(f)); return u;
}
__device__ __forceinline__ void mma_tf32(float c[4],
                                         uint32_t a0, uint32_t a1,
                                         uint32_t a2, uint32_t a3,
                                         uint32_t b0, uint32_t b1) {
    asm volatile(
        "mma.sync.aligned.m16n8k8.row.col.f32.tf32.tf32.f32 "
        "{%0,%1,%2,%3}, {%4,%5,%6,%7}, {%8,%9}, {%0,%1,%2,%3};"
        : "+f"(c[0]), "+f"(c[1]), "+f"(c[2]), "+f"(c[3])
        : "r"(a0), "r"(a1), "r"(a2), "r"(a3), "r"(b0), "r"(b1));
}

// --------------------------------------------------- LayerNorm + bias (fused)
__global__ void k_ln(const float* __restrict__ pair,
                     const float* __restrict__ gamma,
                     const float* __restrict__ beta,
                     const float* __restrict__ Wb)
{
    const int row = blockIdx.x;
    const int t   = threadIdx.x;   // 0..127
    float x = pair[row * CP + t];

    __shared__ float sred[4];
    __shared__ float sbias[4][4];  // [warp][h]
    float s = x;
    #pragma unroll
    for (int off = 16; off; off >>= 1) s += __shfl_xor_sync(0xffffffffu, s, off);
    if ((t & 31) == 0) sred[t >> 5] = s;
    __syncthreads();
    float mu = (sred[0] + sred[1] + sred[2] + sred[3]) * (1.0f / CP);
    __syncthreads();

    float d  = x - mu;
    float sq = d * d;
    #pragma unroll
    for (int off = 16; off; off >>= 1) sq += __shfl_xor_sync(0xffffffffu, sq, off);
    if ((t & 31) == 0) sred[t >> 5] = sq;
    __syncthreads();
    float var = (sred[0] + sred[1] + sred[2] + sred[3]) * (1.0f / CP);

    float pn = d * rsqrtf(var + 1e-5f) * gamma[t] + beta[t];
    g_pn[row * CP + t] = pn;

    float pb[4];
    #pragma unroll
    for (int h = 0; h < 4; ++h) pb[h] = pn * Wb[t * 4 + h];
    #pragma unroll
    for (int h = 0; h < 4; ++h) {
        #pragma unroll
        for (int off = 16; off; off >>= 1)
            pb[h] += __shfl_xor_sync(0xffffffffu, pb[h], off);
    }
    if ((t & 31) == 0) {
        #pragma unroll
        for (int h = 0; h < 4; ++h) sbias[t >> 5][h] = pb[h];
    }
    __syncthreads();
    if (t < 4)
        g_b[t * NN + row] = sbias[0][t] + sbias[1][t] + sbias[2][t] + sbias[3][t];
}

// ------------------------------------------- q/k/v/g projection (tf32 mma.sync)
#define PA_STRIDE 132
#define PB_STRIDE 136
#define PJ_SMEM ((128 * PA_STRIDE + 128 * PB_STRIDE) * 4)

__global__ void __launch_bounds__(256, 1) k_proj_mma(
    const float* __restrict__ Wq, const float* __restrict__ Wk,
    const float* __restrict__ Wv, const float* __restrict__ Wg)
{
    extern __shared__ uint32_t usm[];
    uint32_t* As = usm;                       // [128][132] tf32
    uint32_t* Bs = usm + 128 * PA_STRIDE;     // [128][136] tf32 (k-major)

    const int tid = threadIdx.x;
    const int wid = tid >> 5, lane = tid & 31;
    const int warp_m = wid & 1, warp_n = wid >> 1;
    const int gid = lane >> 2, tig = lane & 3;
    const int m0 = blockIdx.x * 128;

    #pragma unroll
    for (int it = 0; it < 16; ++it) {
        int idx = tid + it * 256;
        int r = idx >> 5, c4 = (idx & 31) << 2;
        float4 v = *(const float4*)&g_pn[(size_t)(m0 + r) * CP + c4];
        uint4 u = make_uint4(f2tf32(v.x), f2tf32(v.y), f2tf32(v.z), f2tf32(v.w));
        *(uint4*)&As[r * PA_STRIDE + c4] = u;
    }

    const float* Ws[4] = {Wq, Wk, Wv, Wg};
    float* Os[4] = {g_q, g_k, g_v, g_g};

    #pragma unroll
    for (int mat = 0; mat < 4; ++mat) {
        #pragma unroll
        for (int it = 0; it < 16; ++it) {
            int idx = tid + it * 256;
            int k = idx >> 5, n4 = (idx & 31) << 2;
            float4 v = *(const float4*)&Ws[mat][(size_t)k * CP + n4];
            uint4 u = make_uint4(f2tf32(v.x), f2tf32(v.y), f2tf32(v.z), f2tf32(v.w));
            *(uint4*)&Bs[k * PB_STRIDE + n4] = u;
        }
        __syncthreads();

        float c[4][4][4];
        #pragma unroll
        for (int mf = 0; mf < 4; ++mf)
            #pragma unroll
            for (int nf = 0; nf < 4; ++nf)
                #pragma unroll
                for (int q = 0; q < 4; ++q) c[mf][nf][q] = 0.f;

        #pragma unroll
        for (int ks = 0; ks < 16; ++ks) {
            const int k0 = ks * 8;
            uint32_t a[4][4], b[4][2];
            #pragma unroll
            for (int mf = 0; mf < 4; ++mf) {
                int r = warp_m * 64 + mf * 16 + gid;
                a[mf][0] = As[r * PA_STRIDE + k0 + tig];
                a[mf][1] = As[(r + 8) * PA_STRIDE + k0 + tig];
                a[mf][2] = As[r * PA_STRIDE + k0 + tig + 4];
                a[mf][3] = As[(r + 8) * PA_STRIDE + k0 + tig + 4];
            }
            #pragma unroll
            for (int nf = 0; nf < 4; ++nf) {
                int n = warp_n * 32 + nf * 8 + gid;
                b[nf][0] = Bs[(k0 + tig) * PB_STRIDE + n];
                b[nf][1] = Bs[(k0 + tig + 4) * PB_STRIDE + n];
            }
            #pragma unroll
            for (int mf = 0; mf < 4; ++mf)
                #pragma unroll
                for (int nf = 0; nf < 4; ++nf)
                    mma_tf32(c[mf][nf], a[mf][0], a[mf][1], a[mf][2], a[mf][3],
                             b[nf][0], b[nf][1]);
        }
        __syncthreads();

        float* O = Os[mat];
        #pragma unroll
        for (int mf = 0; mf < 4; ++mf) {
            #pragma unroll
            for (int nf = 0; nf < 4; ++nf) {
                int r  = m0 + warp_m * 64 + mf * 16 + gid;
                int cb = warp_n * 32 + nf * 8 + 2 * tig;
                float v0 = c[mf][nf][0], v1 = c[mf][nf][1];
                float v2 = c[mf][nf][2], v3 = c[mf][nf][3];
                if (mat == 3) {
                    v0 = 1.f / (1.f + __expf(-v0));
                    v1 = 1.f / (1.f + __expf(-v1));
                    v2 = 1.f / (1.f + __expf(-v2));
                    v3 = 1.f / (1.f + __expf(-v3));
                }
                *(float2*)&O[(size_t)r * CP + cb]       = make_float2(v0, v1);
                *(float2*)&O[(size_t)(r + 8) * CP + cb] = make_float2(v2, v3);
            }
        }
    }
}

// ----------------------------------------------- output projection (tf32 mma)
__global__ void __launch_bounds__(256, 1) k_out_mma(const float* __restrict__ Wout,
                                                    float* __restrict__ out)
{
    extern __shared__ uint32_t usm[];
    uint32_t* As = usm;
    uint32_t* Bs = usm + 128 * PA_STRIDE;

    const int tid = threadIdx.x;
    const int wid = tid >> 5, lane = tid & 31;
    const int warp_m = wid & 1, warp_n = wid >> 1;
    const int gid = lane >> 2, tig = lane & 3;
    const int m0 = blockIdx.x * 128;

    #pragma unroll
    for (int it = 0; it < 16; ++it) {
        int idx = tid + it * 256;
        int r = idx >> 5, c4 = (idx & 31) << 2;
        float4 v = *(const float4*)&g_o[(size_t)(m0 + r) * CP + c4];
        uint4 u = make_uint4(f2tf32(v.x), f2tf32(v.y), f2tf32(v.z), f2tf32(v.w));
        *(uint4*)&As[r * PA_STRIDE + c4] = u;
    }
    #pragma unroll
    for (int it = 0; it < 16; ++it) {
        int idx = tid + it * 256;
        int k = idx >> 5, n4 = (idx & 31) << 2;
        float4 v = *(const float4*)&Wout[(size_t)k * CP + n4];
        uint4 u = make_uint4(f2tf32(v.x), f2tf32(v.y), f2tf32(v.z), f2tf32(v.w));
        *(uint4*)&Bs[k * PB_STRIDE + n4] = u;
    }
    __syncthreads();

    float c[4][4][4];
    #pragma unroll
    for (int mf = 0; mf < 4; ++mf)
        #pragma unroll
        for (int nf = 0; nf < 4; ++nf)
            #pragma unroll
            for (int q = 0; q < 4; ++q) c[mf][nf][q] = 0.f;

    #pragma unroll
    for (int ks = 0; ks < 16; ++ks) {
        const int k0 = ks * 8;
        uint32_t a[4][4], b[4][2];
        #pragma unroll
        for (int mf = 0; mf < 4; ++mf) {
            int r = warp_m * 64 + mf * 16 + gid;
            a[mf][0] = As[r * PA_STRIDE + k0 + tig];
            a[mf][1] = As[(r + 8) * PA_STRIDE + k0 + tig];
            a[mf][2] = As[r * PA_STRIDE + k0 + tig + 4];
            a[mf][3] = As[(r + 8) * PA_STRIDE + k0 + tig + 4];
        }
        #pragma unroll
        for (int nf = 0; nf < 4; ++nf) {
            int n = warp_n * 32 + nf * 8 + gid;
            b[nf][0] = Bs[(k0 + tig) * PB_STRIDE + n];
            b[nf][1] = Bs[(k0 + tig + 4) * PB_STRIDE + n];
        }
        #pragma unroll
        for (int mf = 0; mf < 4; ++mf)
            #pragma unroll
            for (int nf = 0; nf < 4; ++nf)
                mma_tf32(c[mf][nf], a[mf][0], a[mf][1], a[mf][2], a[mf][3],
                         b[nf][0], b[nf][1]);
    }

    #pragma unroll
    for (int mf = 0; mf < 4; ++mf) {
        #pragma unroll
        for (int nf = 0; nf < 4; ++nf) {
            int r  = m0 + warp_m * 64 + mf * 16 + gid;
            int cb = warp_n * 32 + nf * 8 + 2 * tig;
            *(float2*)&out[(size_t)r * CP + cb] =
                make_float2(c[mf][nf][0], c[mf][nf][1]);
            *(float2*)&out[(size_t)(r + 8) * CP + cb] =
                make_float2(c[mf][nf][2], c[mf][nf][3]);
        }
    }
}

// ------------------------------------------------ attention (tf32 mma.sync)
// One CTA per (i,h), 256 threads = 8 warps, 4 j-tiles of 64.
#define KC_S 264
#define V_S  40
#define Q_S  40
#define P_S  264
#define OFF_KC 0
#define OFF_V  (32 * KC_S)
#define OFF_Q  (OFF_V + 256 * V_S)
#define OFF_P  (OFF_Q + 64 * Q_S)
#define OFF_INV (OFF_P + 64 * P_S)
#define ATTN_WORDS (OFF_INV + 64)
#define ATTN_SMEM (ATTN_WORDS * 4)
#define RED_S 34   // partial-tile stride (reuse of P area)

__global__ void __launch_bounds__(256, 1) k_attn_mma()
{
    extern __shared__ uint32_t usm[];
    uint32_t* Kc  = usm + OFF_KC;   // [32][264] tf32, c-major K
    uint32_t* Vs  = usm + OFF_V;    // [256][40] tf32
    uint32_t* Qs  = usm + OFF_Q;    // [64][40]  tf32 (pre-scaled)
    uint32_t* Ps  = usm + OFF_P;    // [64][264] logits -> exp(tf32) -> partials
    float*    invs = (float*)(usm + OFF_INV);

    const int i = blockIdx.x, h = blockIdx.y;
    const int tid = threadIdx.x;
    const int wid = tid >> 5, lane = tid & 31;
    const int gid = lane >> 2, tig = lane & 3;
    const float scale = 0.17677669529663687f;  // 1/sqrt(32)

    const float* gk = g_k + (size_t)(i * 256) * CP + h * 32;
    const float* gv = g_v + (size_t)(i * 256) * CP + h * 32;
    const float* gq = g_q + (size_t)(i * 256) * CP + h * 32;
    const float* gg = g_g + (size_t)(i * 256) * CP + h * 32;
    const float* __restrict__ gb = g_b + (size_t)h * NN;

    // stage K (transposed, c-major) and V (natural) as tf32
    for (int idx = tid; idx < 256 * 8; idx += 256) {
        int kk = idx >> 3, c4 = (idx & 7) << 2;
        float4 kv = *(const float4*)&gk[kk * CP + c4];
        Kc[(c4 + 0) * KC_S + kk] = f2tf32(kv.x);
        Kc[(c4 + 1) * KC_S + kk] = f2tf32(kv.y);
        Kc[(c4 + 2) * KC_S + kk] = f2tf32(kv.z);
        Kc[(c4 + 3) * KC_S + kk] = f2tf32(kv.w);
        float4 vv = *(const float4*)&gv[kk * CP + c4];
        *(uint4*)&Vs[kk * V_S + c4] =
            make_uint4(f2tf32(vv.x), f2tf32(vv.y), f2tf32(vv.z), f2tf32(vv.w));
    }
    __syncthreads();

    for (int jt = 0; jt < 4; ++jt) {
        const int j0 = jt * 64;

        // stage Q tile (scaled, tf32)
        for (int idx = tid; idx < 64 * 8; idx += 256) {
            int r = idx >> 3, c4 = (idx & 7) << 2;
            float4 q = *(const float4*)&gq[(j0 + r) * CP + c4];
            *(uint4*)&Qs[r * Q_S + c4] =
                make_uint4(f2tf32(q.x * scale), f2tf32(q.y * scale),
                           f2tf32(q.z * scale), f2tf32(q.w * scale));
        }
        __syncthreads();

        // ---- S = Q K^T : warp wid covers cols wid*32..+31, rows 0..63 ----
        {
            float c[4][4][4];
            #pragma unroll
            for (int mf = 0; mf < 4; ++mf)
                #pragma unroll
                for (int nf = 0; nf < 4; ++nf)
                    #pragma unroll
                    for (int q = 0; q < 4; ++q) c[mf][nf][q] = 0.f;

            #pragma unroll
            for (int ks = 0; ks < 4; ++ks) {
                const int c0 = ks * 8;
                uint32_t a[4][4], b[4][2];
                #pragma unroll
                for (int mf = 0; mf < 4; ++mf) {
                    int r = mf * 16 + gid;
                    a[mf][0] = Qs[r * Q_S + c0 + tig];
                    a[mf][1] = Qs[(r + 8) * Q_S + c0 + tig];
                    a[mf][2] = Qs[r * Q_S + c0 + tig + 4];
                    a[mf][3] = Qs[(r + 8) * Q_S + c0 + tig + 4];
                }
                #pragma unroll
                for (int nf = 0; nf < 4; ++nf) {
                    int n = wid * 32 + nf * 8 + gid;
                    b[nf][0] = Kc[(c0 + tig) * KC_S + n];
                    b[nf][1] = Kc[(c0 + tig + 4) * KC_S + n];
                }
                #pragma unroll
                for (int mf = 0; mf < 4; ++mf)
                    #pragma unroll
                    for (int nf = 0; nf < 4; ++nf)
                        mma_tf32(c[mf][nf], a[mf][0], a[mf][1], a[mf][2], a[mf][3],
                                 b[nf][0], b[nf][1]);
            }

            #pragma unroll
            for (int mf = 0; mf < 4; ++mf)
                #pragma unroll
                for (int nf = 0; nf < 4; ++nf) {
                    int r  = mf * 16 + gid;
                    int cb = wid * 32 + nf * 8 + 2 * tig;
                    *(float2*)&Ps[r * P_S + cb] =
                        make_float2(c[mf][nf][0], c[mf][nf][1]);
                    *(float2*)&Ps[(r + 8) * P_S + cb] =
                        make_float2(c[mf][nf][2], c[mf][nf][3]);
                }
        }
        __syncthreads();

        // ---- SIMT softmax: warp owns rows wid*8..+7 (full 256 cols) ----
        #pragma unroll
        for (int rr = 0; rr < 8; ++rr) {
            const int r = wid * 8 + rr;
            const int jglob = j0 + r;
            float v[8];
            #pragma unroll
            for (int u = 0; u < 8; ++u)
                v[u] = __uint_as_float(Ps[r * P_S + lane + 32 * u])
                     + __ldg(&gb[jglob * 256 + lane + 32 * u]);
            float m = v[0];
            #pragma unroll
            for (int u = 1; u < 8; ++u) m = fmaxf(m, v[u]);
            #pragma unroll
            for (int off = 16; off; off >>= 1)
                m = fmaxf(m, __shfl_xor_sync(0xffffffffu, m, off));
            float s = 0.f;
            #pragma unroll
            for (int u = 0; u < 8; ++u) {
                uint32_t uq = f2tf32(__expf(v[u] - m));
                Ps[r * P_S + lane + 32 * u] = uq;
                s += __uint_as_float(uq);
            }
            #pragma unroll
            for (int off = 16; off; off >>= 1)
                s += __shfl_xor_sync(0xffffffffu, s, off);
            if (lane == 0) invs[r] = 1.f / s;
        }
        __syncthreads();

        // ---- O = P V : warp (wm = wid>>2, wk = wid&3) ----
        const int wm = wid >> 2, wk = wid & 3;
        float o[2][4][4];
        #pragma unroll
        for (int mf = 0; mf < 2; ++mf)
            #pragma unroll
            for (int nf = 0; nf < 4; ++nf)
                #pragma unroll
                for (int q = 0; q < 4; ++q) o[mf][nf][q] = 0.f;

        #pragma unroll
        for (int ks = 0; ks < 8; ++ks) {
            const int k0 = wk * 64 + ks * 8;
            uint32_t a[2][4], b[4][2];
            #pragma unroll
            for (int mf = 0; mf < 2; ++mf) {
                int r = wm * 32 + mf * 16 + gid;
                a[mf][0] = Ps[r * P_S + k0 + tig];
                a[mf][1] = Ps[(r + 8) * P_S + k0 + tig];
                a[mf][2] = Ps[r * P_S + k0 + tig + 4];
                a[mf][3] = Ps[(r + 8) * P_S + k0 + tig + 4];
            }
            #pragma unroll
            for (int nf = 0; nf < 4; ++nf) {
                int n = nf * 8 + gid;
                b[nf][0] = Vs[(k0 + tig) * V_S + n];
                b[nf][1] = Vs[(k0 + tig + 4) * V_S + n];
            }
            #pragma unroll
            for (int mf = 0; mf < 2; ++mf)
                #pragma unroll
                for (int nf = 0; nf < 4; ++nf)
                    mma_tf32(o[mf][nf], a[mf][0], a[mf][1], a[mf][2], a[mf][3],
                             b[nf][0], b[nf][1]);
        }
        __syncthreads();   // all P reads done -> reuse Ps for partials

        // write partial tiles: red[wid][32][RED_S]
        {
            uint32_t* red = Ps + wid * 32 * RED_S;
            #pragma unroll
            for (int mf = 0; mf < 2; ++mf)
                #pragma unroll
                for (int nf = 0; nf < 4; ++nf) {
                    int r2 = mf * 16 + gid;
                    int cb = nf * 8 + 2 * tig;
                    *(float2*)&red[r2 * RED_S + cb] =
                        make_float2(o[mf][nf][0], o[mf][nf][1]);
                    *(float2*)&red[(r2 + 8) * RED_S + cb] =
                        make_float2(o[mf][nf][2], o[mf][nf][3]);
                }
        }
        __syncthreads();

        // reduce partials over wk, apply 1/sum and gate, write out
        #pragma unroll
        for (int e = 0; e < 8; ++e) {
            int idx = tid + e * 256;
            int r = idx >> 5, c = idx & 31;      // r 0..63
            int wm2 = r >> 5, r2 = r & 31;
            float s = 0.f;
            #pragma unroll
            for (int wk2 = 0; wk2 < 4; ++wk2)
                s += __uint_as_float(
                    Ps[(wm2 * 4 + wk2) * 32 * RED_S + r2 * RED_S + c]);
            int j = j0 + r;
            s *= invs[r];
            s *= gg[j * CP + c];
            g_o[(size_t)(i * 256 + j) * CP + h * 32 + c] = s;
        }
        __syncthreads();
    }
}

// ----------------------------------------------------------------- launcher
extern "C" void kernel_launch(void* const* d_in, const int* in_sizes, int n_in,
                              void* d_out, int out_size)
{
    const float* pair  = (const float*)d_in[0];
    const float* gamma = (const float*)d_in[1];
    const float* beta  = (const float*)d_in[2];
    const float* Wq    = (const float*)d_in[3];
    const float* Wk    = (const float*)d_in[4];
    const float* Wv    = (const float*)d_in[5];
    const float* Wb    = (const float*)d_in[6];
    const float* Wg    = (const float*)d_in[7];
    const float* Wout  = (const float*)d_in[8];
    float* out = (float*)d_out;

    cudaFuncSetAttribute(k_proj_mma, cudaFuncAttributeMaxDynamicSharedMemorySize, PJ_SMEM);
    cudaFuncSetAttribute(k_out_mma,  cudaFuncAttributeMaxDynamicSharedMemorySize, PJ_SMEM);
    cudaFuncSetAttribute(k_attn_mma, cudaFuncAttributeMaxDynamicSharedMemorySize, ATTN_SMEM);

    k_ln      <<<NN, 128>>>(pair, gamma, beta, Wb);
    k_proj_mma<<<NN / 128, 256, PJ_SMEM>>>(Wq, Wk, Wv, Wg);
    k_attn_mma<<<dim3(N_TOKEN, H), 256, ATTN_SMEM>>>();
    k_out_mma <<<NN / 128, 256, PJ_SMEM>>>(Wout, out);
}

// round 6
// speedup vs baseline: 4.4601x; 1.4424x over previous
#include <cuda_runtime.h>
#include <math.h>
#include <cstdint>

#define N_TOKEN 256
#define CP 128
#define H 4
#define NN (N_TOKEN * N_TOKEN)

// Scratch (allocation-free: __device__ globals)
__device__ float g_pn[NN * CP];   // layernormed pair
__device__ float g_q [NN * CP];   // [i,j,h*32+c]
__device__ float g_k [NN * CP];
__device__ float g_v [NN * CP];
__device__ float g_g [NN * CP];   // sigmoid gate
__device__ float g_b [H * NN];    // [h][j*256+k]
__device__ float g_o [NN * CP];   // gated attention output

// --------------------------------------------------------------- mma helpers
__device__ __forceinline__ uint32_t f2tf32(float f) {
    uint32_t u; asm("cvt.rna.tf32.f32 %0, %1;" : "=r"(u) : "f"(f)); return u;
}
__device__ __forceinline__ void mma_tf32(float c[4],
                                         uint32_t a0, uint32_t a1,
                                         uint32_t a2, uint32_t a3,
                                         uint32_t b0, uint32_t b1) {
    asm volatile(
        "mma.sync.aligned.m16n8k8.row.col.f32.tf32.tf32.f32 "
        "{%0,%1,%2,%3}, {%4,%5,%6,%7}, {%8,%9}, {%0,%1,%2,%3};"
        : "+f"(c[0]), "+f"(c[1]), "+f"(c[2]), "+f"(c[3])
        : "r"(a0), "r"(a1), "r"(a2), "r"(a3), "r"(b0), "r"(b1));
}

// ---------------------------------- LayerNorm + bias (warp-local, 8 rows/CTA)
__global__ void __launch_bounds__(256) k_ln(const float* __restrict__ pair,
                     const float* __restrict__ gamma,
                     const float* __restrict__ beta,
                     const float* __restrict__ Wb)
{
    const int w    = threadIdx.x >> 5, lane = threadIdx.x & 31;
    const int row  = blockIdx.x * 8 + w;

    float4 x = *(const float4*)&pair[(size_t)row * CP + lane * 4];
    float s = x.x + x.y + x.z + x.w;
    #pragma unroll
    for (int off = 16; off; off >>= 1) s += __shfl_xor_sync(0xffffffffu, s, off);
    float mu = s * (1.0f / CP);

    float4 d = make_float4(x.x - mu, x.y - mu, x.z - mu, x.w - mu);
    float sq = d.x * d.x + d.y * d.y + d.z * d.z + d.w * d.w;
    #pragma unroll
    for (int off = 16; off; off >>= 1) sq += __shfl_xor_sync(0xffffffffu, sq, off);
    float rstd = rsqrtf(sq * (1.0f / CP) + 1e-5f);

    float4 ga = *(const float4*)&gamma[lane * 4];
    float4 be = *(const float4*)&beta[lane * 4];
    float4 pn;
    pn.x = d.x * rstd * ga.x + be.x;
    pn.y = d.y * rstd * ga.y + be.y;
    pn.z = d.z * rstd * ga.z + be.z;
    pn.w = d.w * rstd * ga.w + be.w;
    *(float4*)&g_pn[(size_t)row * CP + lane * 4] = pn;

    float pe[4] = {pn.x, pn.y, pn.z, pn.w};
    float pb[4] = {0.f, 0.f, 0.f, 0.f};
    #pragma unroll
    for (int e = 0; e < 4; ++e) {
        float4 wb = *(const float4*)&Wb[(lane * 4 + e) * 4];
        pb[0] += pe[e] * wb.x; pb[1] += pe[e] * wb.y;
        pb[2] += pe[e] * wb.z; pb[3] += pe[e] * wb.w;
    }
    #pragma unroll
    for (int h = 0; h < 4; ++h) {
        #pragma unroll
        for (int off = 16; off; off >>= 1)
            pb[h] += __shfl_xor_sync(0xffffffffu, pb[h], off);
    }
    if (lane < 4) g_b[lane * NN + row] = pb[lane];
}

// ------------------------------------------- q/k/v/g projection (tf32 mma.sync)
// 64-row m-tile, 2 CTAs/SM. 8 warps: warp_m = wid&1 (32 rows), warp_n (32 cols).
#define PA_STRIDE 132
#define PB_STRIDE 136
#define PJ_SMEM ((64 * PA_STRIDE + 128 * PB_STRIDE) * 4)

__global__ void __launch_bounds__(256, 2) k_proj_mma(
    const float* __restrict__ Wq, const float* __restrict__ Wk,
    const float* __restrict__ Wv, const float* __restrict__ Wg)
{
    extern __shared__ uint32_t usm[];
    uint32_t* As = usm;                      // [64][132] tf32
    uint32_t* Bs = usm + 64 * PA_STRIDE;     // [128][136] tf32 (k-major)

    const int tid = threadIdx.x;
    const int wid = tid >> 5, lane = tid & 31;
    const int warp_m = wid & 1, warp_n = wid >> 1;
    const int gid = lane >> 2, tig = lane & 3;
    const int m0 = blockIdx.x * 64;

    #pragma unroll
    for (int it = 0; it < 8; ++it) {
        int idx = tid + it * 256;            // 0..2047
        int r = idx >> 5, c4 = (idx & 31) << 2;
        float4 v = *(const float4*)&g_pn[(size_t)(m0 + r) * CP + c4];
        uint4 u = make_uint4(f2tf32(v.x), f2tf32(v.y), f2tf32(v.z), f2tf32(v.w));
        *(uint4*)&As[r * PA_STRIDE + c4] = u;
    }

    const float* Ws[4] = {Wq, Wk, Wv, Wg};
    float* Os[4] = {g_q, g_k, g_v, g_g};

    #pragma unroll
    for (int mat = 0; mat < 4; ++mat) {
        #pragma unroll
        for (int it = 0; it < 16; ++it) {
            int idx = tid + it * 256;
            int k = idx >> 5, n4 = (idx & 31) << 2;
            float4 v = *(const float4*)&Ws[mat][(size_t)k * CP + n4];
            uint4 u = make_uint4(f2tf32(v.x), f2tf32(v.y), f2tf32(v.z), f2tf32(v.w));
            *(uint4*)&Bs[k * PB_STRIDE + n4] = u;
        }
        __syncthreads();

        float c[2][4][4];
        #pragma unroll
        for (int mf = 0; mf < 2; ++mf)
            #pragma unroll
            for (int nf = 0; nf < 4; ++nf)
                #pragma unroll
                for (int q = 0; q < 4; ++q) c[mf][nf][q] = 0.f;

        #pragma unroll
        for (int ks = 0; ks < 16; ++ks) {
            const int k0 = ks * 8;
            uint32_t a[2][4], b[4][2];
            #pragma unroll
            for (int mf = 0; mf < 2; ++mf) {
                int r = warp_m * 32 + mf * 16 + gid;
                a[mf][0] = As[r * PA_STRIDE + k0 + tig];
                a[mf][1] = As[(r + 8) * PA_STRIDE + k0 + tig];
                a[mf][2] = As[r * PA_STRIDE + k0 + tig + 4];
                a[mf][3] = As[(r + 8) * PA_STRIDE + k0 + tig + 4];
            }
            #pragma unroll
            for (int nf = 0; nf < 4; ++nf) {
                int n = warp_n * 32 + nf * 8 + gid;
                b[nf][0] = Bs[(k0 + tig) * PB_STRIDE + n];
                b[nf][1] = Bs[(k0 + tig + 4) * PB_STRIDE + n];
            }
            #pragma unroll
            for (int mf = 0; mf < 2; ++mf)
                #pragma unroll
                for (int nf = 0; nf < 4; ++nf)
                    mma_tf32(c[mf][nf], a[mf][0], a[mf][1], a[mf][2], a[mf][3],
                             b[nf][0], b[nf][1]);
        }
        __syncthreads();

        float* O = Os[mat];
        #pragma unroll
        for (int mf = 0; mf < 2; ++mf) {
            #pragma unroll
            for (int nf = 0; nf < 4; ++nf) {
                int r  = m0 + warp_m * 32 + mf * 16 + gid;
                int cb = warp_n * 32 + nf * 8 + 2 * tig;
                float v0 = c[mf][nf][0], v1 = c[mf][nf][1];
                float v2 = c[mf][nf][2], v3 = c[mf][nf][3];
                if (mat == 3) {
                    v0 = 1.f / (1.f + __expf(-v0));
                    v1 = 1.f / (1.f + __expf(-v1));
                    v2 = 1.f / (1.f + __expf(-v2));
                    v3 = 1.f / (1.f + __expf(-v3));
                }
                *(float2*)&O[(size_t)r * CP + cb]       = make_float2(v0, v1);
                *(float2*)&O[(size_t)(r + 8) * CP + cb] = make_float2(v2, v3);
            }
        }
    }
}

// ----------------------------------------------- output projection (tf32 mma)
__global__ void __launch_bounds__(256, 2) k_out_mma(const float* __restrict__ Wout,
                                                    float* __restrict__ out)
{
    extern __shared__ uint32_t usm[];
    uint32_t* As = usm;
    uint32_t* Bs = usm + 64 * PA_STRIDE;

    const int tid = threadIdx.x;
    const int wid = tid >> 5, lane = tid & 31;
    const int warp_m = wid & 1, warp_n = wid >> 1;
    const int gid = lane >> 2, tig = lane & 3;
    const int m0 = blockIdx.x * 64;

    #pragma unroll
    for (int it = 0; it < 8; ++it) {
        int idx = tid + it * 256;
        int r = idx >> 5, c4 = (idx & 31) << 2;
        float4 v = *(const float4*)&g_o[(size_t)(m0 + r) * CP + c4];
        uint4 u = make_uint4(f2tf32(v.x), f2tf32(v.y), f2tf32(v.z), f2tf32(v.w));
        *(uint4*)&As[r * PA_STRIDE + c4] = u;
    }
    #pragma unroll
    for (int it = 0; it < 16; ++it) {
        int idx = tid + it * 256;
        int k = idx >> 5, n4 = (idx & 31) << 2;
        float4 v = *(const float4*)&Wout[(size_t)k * CP + n4];
        uint4 u = make_uint4(f2tf32(v.x), f2tf32(v.y), f2tf32(v.z), f2tf32(v.w));
        *(uint4*)&Bs[k * PB_STRIDE + n4] = u;
    }
    __syncthreads();

    float c[2][4][4];
    #pragma unroll
    for (int mf = 0; mf < 2; ++mf)
        #pragma unroll
        for (int nf = 0; nf < 4; ++nf)
            #pragma unroll
            for (int q = 0; q < 4; ++q) c[mf][nf][q] = 0.f;

    #pragma unroll
    for (int ks = 0; ks < 16; ++ks) {
        const int k0 = ks * 8;
        uint32_t a[2][4], b[4][2];
        #pragma unroll
        for (int mf = 0; mf < 2; ++mf) {
            int r = warp_m * 32 + mf * 16 + gid;
            a[mf][0] = As[r * PA_STRIDE + k0 + tig];
            a[mf][1] = As[(r + 8) * PA_STRIDE + k0 + tig];
            a[mf][2] = As[r * PA_STRIDE + k0 + tig + 4];
            a[mf][3] = As[(r + 8) * PA_STRIDE + k0 + tig + 4];
        }
        #pragma unroll
        for (int nf = 0; nf < 4; ++nf) {
            int n = warp_n * 32 + nf * 8 + gid;
            b[nf][0] = Bs[(k0 + tig) * PB_STRIDE + n];
            b[nf][1] = Bs[(k0 + tig + 4) * PB_STRIDE + n];
        }
        #pragma unroll
        for (int mf = 0; mf < 2; ++mf)
            #pragma unroll
            for (int nf = 0; nf < 4; ++nf)
                mma_tf32(c[mf][nf], a[mf][0], a[mf][1], a[mf][2], a[mf][3],
                         b[nf][0], b[nf][1]);
    }

    #pragma unroll
    for (int mf = 0; mf < 2; ++mf) {
        #pragma unroll
        for (int nf = 0; nf < 4; ++nf) {
            int r  = m0 + warp_m * 32 + mf * 16 + gid;
            int cb = warp_n * 32 + nf * 8 + 2 * tig;
            *(float2*)&out[(size_t)r * CP + cb] =
                make_float2(c[mf][nf][0], c[mf][nf][1]);
            *(float2*)&out[(size_t)(r + 8) * CP + cb] =
                make_float2(c[mf][nf][2], c[mf][nf][3]);
        }
    }
}

// ------------------------------------------------ attention (tf32 mma.sync)
// One CTA per (i,h), 256 threads = 8 warps, 8 j-tiles of 32, 2 CTAs/SM.
#define KC_S 264
#define V_S  40
#define Q_S  40
#define P_S  264
#define JT   32
#define OFF_KC 0
#define OFF_V  (32 * KC_S)
#define OFF_Q  (OFF_V + 256 * V_S)
#define OFF_P  (OFF_Q + JT * Q_S)
#define OFF_INV (OFF_P + JT * P_S)
#define ATTN_WORDS (OFF_INV + JT)
#define ATTN_SMEM (ATTN_WORDS * 4)
#define RED_S 34   // partial-tile stride (reuse of P area)

__global__ void __launch_bounds__(256, 2) k_attn_mma()
{
    extern __shared__ uint32_t usm[];
    uint32_t* Kc  = usm + OFF_KC;   // [32][264] tf32, c-major K
    uint32_t* Vs  = usm + OFF_V;    // [256][40] tf32
    uint32_t* Qs  = usm + OFF_Q;    // [32][40]  tf32 (pre-scaled)
    uint32_t* Ps  = usm + OFF_P;    // [32][264] logits -> exp(tf32) -> partials
    float*    invs = (float*)(usm + OFF_INV);

    const int i = blockIdx.x, h = blockIdx.y;
    const int tid = threadIdx.x;
    const int wid = tid >> 5, lane = tid & 31;
    const int gid = lane >> 2, tig = lane & 3;
    const float scale = 0.17677669529663687f;  // 1/sqrt(32)

    const float* gk = g_k + (size_t)(i * 256) * CP + h * 32;
    const float* gv = g_v + (size_t)(i * 256) * CP + h * 32;
    const float* gq = g_q + (size_t)(i * 256) * CP + h * 32;
    const float* gg = g_g + (size_t)(i * 256) * CP + h * 32;
    const float* __restrict__ gb = g_b + (size_t)h * NN;

    // stage K (transposed, c-major) and V (natural) as tf32
    for (int idx = tid; idx < 256 * 8; idx += 256) {
        int kk = idx >> 3, c4 = (idx & 7) << 2;
        float4 kv = *(const float4*)&gk[kk * CP + c4];
        Kc[(c4 + 0) * KC_S + kk] = f2tf32(kv.x);
        Kc[(c4 + 1) * KC_S + kk] = f2tf32(kv.y);
        Kc[(c4 + 2) * KC_S + kk] = f2tf32(kv.z);
        Kc[(c4 + 3) * KC_S + kk] = f2tf32(kv.w);
        float4 vv = *(const float4*)&gv[kk * CP + c4];
        *(uint4*)&Vs[kk * V_S + c4] =
            make_uint4(f2tf32(vv.x), f2tf32(vv.y), f2tf32(vv.z), f2tf32(vv.w));
    }
    __syncthreads();

    for (int jt = 0; jt < 8; ++jt) {
        const int j0 = jt * JT;

        // stage Q tile (scaled, tf32): 32 rows x 8 float4
        {
            int r = tid >> 3, c4 = (tid & 7) << 2;
            float4 q = *(const float4*)&gq[(j0 + r) * CP + c4];
            *(uint4*)&Qs[r * Q_S + c4] =
                make_uint4(f2tf32(q.x * scale), f2tf32(q.y * scale),
                           f2tf32(q.z * scale), f2tf32(q.w * scale));
        }
        __syncthreads();

        // ---- S = Q K^T : warp wid covers cols wid*32..+31, rows 0..31 ----
        {
            float c[2][4][4];
            #pragma unroll
            for (int mf = 0; mf < 2; ++mf)
                #pragma unroll
                for (int nf = 0; nf < 4; ++nf)
                    #pragma unroll
                    for (int q = 0; q < 4; ++q) c[mf][nf][q] = 0.f;

            #pragma unroll
            for (int ks = 0; ks < 4; ++ks) {
                const int c0 = ks * 8;
                uint32_t a[2][4], b[4][2];
                #pragma unroll
                for (int mf = 0; mf < 2; ++mf) {
                    int r = mf * 16 + gid;
                    a[mf][0] = Qs[r * Q_S + c0 + tig];
                    a[mf][1] = Qs[(r + 8) * Q_S + c0 + tig];
                    a[mf][2] = Qs[r * Q_S + c0 + tig + 4];
                    a[mf][3] = Qs[(r + 8) * Q_S + c0 + tig + 4];
                }
                #pragma unroll
                for (int nf = 0; nf < 4; ++nf) {
                    int n = wid * 32 + nf * 8 + gid;
                    b[nf][0] = Kc[(c0 + tig) * KC_S + n];
                    b[nf][1] = Kc[(c0 + tig + 4) * KC_S + n];
                }
                #pragma unroll
                for (int mf = 0; mf < 2; ++mf)
                    #pragma unroll
                    for (int nf = 0; nf < 4; ++nf)
                        mma_tf32(c[mf][nf], a[mf][0], a[mf][1], a[mf][2], a[mf][3],
                                 b[nf][0], b[nf][1]);
            }

            #pragma unroll
            for (int mf = 0; mf < 2; ++mf)
                #pragma unroll
                for (int nf = 0; nf < 4; ++nf) {
                    int r  = mf * 16 + gid;
                    int cb = wid * 32 + nf * 8 + 2 * tig;
                    *(float2*)&Ps[r * P_S + cb] =
                        make_float2(c[mf][nf][0], c[mf][nf][1]);
                    *(float2*)&Ps[(r + 8) * P_S + cb] =
                        make_float2(c[mf][nf][2], c[mf][nf][3]);
                }
        }
        __syncthreads();

        // ---- SIMT softmax: warp owns rows wid*4..+3 (full 256 cols) ----
        #pragma unroll
        for (int rr = 0; rr < 4; ++rr) {
            const int r = wid * 4 + rr;
            const int jglob = j0 + r;
            float v[8];
            #pragma unroll
            for (int u = 0; u < 8; ++u)
                v[u] = __uint_as_float(Ps[r * P_S + lane + 32 * u])
                     + __ldg(&gb[jglob * 256 + lane + 32 * u]);
            float m = v[0];
            #pragma unroll
            for (int u = 1; u < 8; ++u) m = fmaxf(m, v[u]);
            #pragma unroll
            for (int off = 16; off; off >>= 1)
                m = fmaxf(m, __shfl_xor_sync(0xffffffffu, m, off));
            float s = 0.f;
            #pragma unroll
            for (int u = 0; u < 8; ++u) {
                uint32_t uq = f2tf32(__expf(v[u] - m));
                Ps[r * P_S + lane + 32 * u] = uq;
                s += __uint_as_float(uq);
            }
            #pragma unroll
            for (int off = 16; off; off >>= 1)
                s += __shfl_xor_sync(0xffffffffu, s, off);
            if (lane == 0) invs[r] = 1.f / s;
        }
        __syncthreads();

        // ---- O = P V : warp (wm = wid>>2 -> 16 rows, wk = wid&3 -> 64 k) ----
        const int wm = wid >> 2, wk = wid & 3;
        float o[4][4];
        #pragma unroll
        for (int nf = 0; nf < 4; ++nf)
            #pragma unroll
            for (int q = 0; q < 4; ++q) o[nf][q] = 0.f;

        #pragma unroll
        for (int ks = 0; ks < 8; ++ks) {
            const int k0 = wk * 64 + ks * 8;
            uint32_t a[4], b[4][2];
            {
                int r = wm * 16 + gid;
                a[0] = Ps[r * P_S + k0 + tig];
                a[1] = Ps[(r + 8) * P_S + k0 + tig];
                a[2] = Ps[r * P_S + k0 + tig + 4];
                a[3] = Ps[(r + 8) * P_S + k0 + tig + 4];
            }
            #pragma unroll
            for (int nf = 0; nf < 4; ++nf) {
                int n = nf * 8 + gid;
                b[nf][0] = Vs[(k0 + tig) * V_S + n];
                b[nf][1] = Vs[(k0 + tig + 4) * V_S + n];
            }
            #pragma unroll
            for (int nf = 0; nf < 4; ++nf)
                mma_tf32(o[nf], a[0], a[1], a[2], a[3], b[nf][0], b[nf][1]);
        }
        __syncthreads();   // all P reads done -> reuse Ps for partials

        // write partial tiles: red[wid][16][RED_S]
        {
            uint32_t* red = Ps + wid * 16 * RED_S;
            #pragma unroll
            for (int nf = 0; nf < 4; ++nf) {
                int cb = nf * 8 + 2 * tig;
                *(float2*)&red[gid * RED_S + cb] = make_float2(o[nf][0], o[nf][1]);
                *(float2*)&red[(gid + 8) * RED_S + cb] = make_float2(o[nf][2], o[nf][3]);
            }
        }
        __syncthreads();

        // reduce partials over wk, apply 1/sum and gate, write out
        #pragma unroll
        for (int e = 0; e < 4; ++e) {
            int idx = tid + e * 256;
            int r = idx >> 5, c = idx & 31;      // r 0..31
            int wm2 = r >> 4, r2 = r & 15;
            float s = 0.f;
            #pragma unroll
            for (int wk2 = 0; wk2 < 4; ++wk2)
                s += __uint_as_float(
                    Ps[(wm2 * 4 + wk2) * 16 * RED_S + r2 * RED_S + c]);
            int j = j0 + r;
            s *= invs[r];
            s *= gg[j * CP + c];
            g_o[(size_t)(i * 256 + j) * CP + h * 32 + c] = s;
        }
        __syncthreads();
    }
}

// ----------------------------------------------------------------- launcher
extern "C" void kernel_launch(void* const* d_in, const int* in_sizes, int n_in,
                              void* d_out, int out_size)
{
    const float* pair  = (const float*)d_in[0];
    const float* gamma = (const float*)d_in[1];
    const float* beta  = (const float*)d_in[2];
    const float* Wq    = (const float*)d_in[3];
    const float* Wk    = (const float*)d_in[4];
    const float* Wv    = (const float*)d_in[5];
    const float* Wb    = (const float*)d_in[6];
    const float* Wg    = (const float*)d_in[7];
    const float* Wout  = (const float*)d_in[8];
    float* out = (float*)d_out;

    cudaFuncSetAttribute(k_proj_mma, cudaFuncAttributeMaxDynamicSharedMemorySize, PJ_SMEM);
    cudaFuncSetAttribute(k_out_mma,  cudaFuncAttributeMaxDynamicSharedMemorySize, PJ_SMEM);
    cudaFuncSetAttribute(k_attn_mma, cudaFuncAttributeMaxDynamicSharedMemorySize, ATTN_SMEM);

    k_ln      <<<NN / 8, 256>>>(pair, gamma, beta, Wb);
    k_proj_mma<<<NN / 64, 256, PJ_SMEM>>>(Wq, Wk, Wv, Wg);
    k_attn_mma<<<dim3(N_TOKEN, H), 256, ATTN_SMEM>>>();
    k_out_mma <<<NN / 64, 256, PJ_SMEM>>>(Wout, out);
}

// round 7
// speedup vs baseline: 4.5951x; 1.0303x over previous
#include <cuda_runtime.h>
#include <math.h>
#include <cstdint>

#define N_TOKEN 256
#define CP 128
#define H 4
#define NN (N_TOKEN * N_TOKEN)

// Scratch (allocation-free: __device__ globals)
__device__ float g_pn[NN * CP];   // layernormed pair
__device__ float g_q [NN * CP];   // [i,j,h*32+c]
__device__ float g_k [NN * CP];
__device__ float g_v [NN * CP];
__device__ float g_g [NN * CP];   // sigmoid gate
__device__ float g_b [H * NN];    // [h][j*256+k]
__device__ float g_o [NN * CP];   // gated attention output

// --------------------------------------------------------------- mma helpers
__device__ __forceinline__ uint32_t f2tf32(float f) {
    uint32_t u; asm("cvt.rna.tf32.f32 %0, %1;" : "=r"(u) : "f"(f)); return u;
}
__device__ __forceinline__ void mma_tf32(float c[4],
                                         uint32_t a0, uint32_t a1,
                                         uint32_t a2, uint32_t a3,
                                         uint32_t b0, uint32_t b1) {
    asm volatile(
        "mma.sync.aligned.m16n8k8.row.col.f32.tf32.tf32.f32 "
        "{%0,%1,%2,%3}, {%4,%5,%6,%7}, {%8,%9}, {%0,%1,%2,%3};"
        : "+f"(c[0]), "+f"(c[1]), "+f"(c[2]), "+f"(c[3])
        : "r"(a0), "r"(a1), "r"(a2), "r"(a3), "r"(b0), "r"(b1));
}

// ---------------------------------- LayerNorm + bias (warp-local, 8 rows/CTA)
__global__ void __launch_bounds__(256) k_ln(const float* __restrict__ pair,
                     const float* __restrict__ gamma,
                     const float* __restrict__ beta,
                     const float* __restrict__ Wb)
{
    const int w    = threadIdx.x >> 5, lane = threadIdx.x & 31;
    const int row  = blockIdx.x * 8 + w;

    float4 x = *(const float4*)&pair[(size_t)row * CP + lane * 4];
    float s = x.x + x.y + x.z + x.w;
    #pragma unroll
    for (int off = 16; off; off >>= 1) s += __shfl_xor_sync(0xffffffffu, s, off);
    float mu = s * (1.0f / CP);

    float4 d = make_float4(x.x - mu, x.y - mu, x.z - mu, x.w - mu);
    float sq = d.x * d.x + d.y * d.y + d.z * d.z + d.w * d.w;
    #pragma unroll
    for (int off = 16; off; off >>= 1) sq += __shfl_xor_sync(0xffffffffu, sq, off);
    float rstd = rsqrtf(sq * (1.0f / CP) + 1e-5f);

    float4 ga = *(const float4*)&gamma[lane * 4];
    float4 be = *(const float4*)&beta[lane * 4];
    float4 pn;
    pn.x = d.x * rstd * ga.x + be.x;
    pn.y = d.y * rstd * ga.y + be.y;
    pn.z = d.z * rstd * ga.z + be.z;
    pn.w = d.w * rstd * ga.w + be.w;
    *(float4*)&g_pn[(size_t)row * CP + lane * 4] = pn;

    float pe[4] = {pn.x, pn.y, pn.z, pn.w};
    float pb[4] = {0.f, 0.f, 0.f, 0.f};
    #pragma unroll
    for (int e = 0; e < 4; ++e) {
        float4 wb = *(const float4*)&Wb[(lane * 4 + e) * 4];
        pb[0] += pe[e] * wb.x; pb[1] += pe[e] * wb.y;
        pb[2] += pe[e] * wb.z; pb[3] += pe[e] * wb.w;
    }
    #pragma unroll
    for (int h = 0; h < 4; ++h) {
        #pragma unroll
        for (int off = 16; off; off >>= 1)
            pb[h] += __shfl_xor_sync(0xffffffffu, pb[h], off);
    }
    if (lane < 4) g_b[lane * NN + row] = pb[lane];
}

// ------------------------------------------- q/k/v/g projection (tf32 mma.sync)
// 64-row m-tile, B staged in two 64-row k-halves -> 3 CTAs/SM.
#define PA_STRIDE 132
#define PB_STRIDE 136
#define PJ_SMEM ((64 * PA_STRIDE + 64 * PB_STRIDE) * 4)

__global__ void __launch_bounds__(256, 3) k_proj_mma(
    const float* __restrict__ Wq, const float* __restrict__ Wk,
    const float* __restrict__ Wv, const float* __restrict__ Wg)
{
    extern __shared__ uint32_t usm[];
    uint32_t* As = usm;                      // [64][132] tf32
    uint32_t* Bs = usm + 64 * PA_STRIDE;     // [64][136] tf32 (k-major half)

    const int tid = threadIdx.x;
    const int wid = tid >> 5, lane = tid & 31;
    const int warp_m = wid & 1, warp_n = wid >> 1;
    const int gid = lane >> 2, tig = lane & 3;
    const int m0 = blockIdx.x * 64;

    #pragma unroll
    for (int it = 0; it < 8; ++it) {
        int idx = tid + it * 256;            // 0..2047
        int r = idx >> 5, c4 = (idx & 31) << 2;
        float4 v = *(const float4*)&g_pn[(size_t)(m0 + r) * CP + c4];
        uint4 u = make_uint4(f2tf32(v.x), f2tf32(v.y), f2tf32(v.z), f2tf32(v.w));
        *(uint4*)&As[r * PA_STRIDE + c4] = u;
    }

    const float* Ws[4] = {Wq, Wk, Wv, Wg};
    float* Os[4] = {g_q, g_k, g_v, g_g};

    #pragma unroll
    for (int mat = 0; mat < 4; ++mat) {
        float c[2][4][4];
        #pragma unroll
        for (int mf = 0; mf < 2; ++mf)
            #pragma unroll
            for (int nf = 0; nf < 4; ++nf)
                #pragma unroll
                for (int q = 0; q < 4; ++q) c[mf][nf][q] = 0.f;

        #pragma unroll
        for (int kh = 0; kh < 2; ++kh) {
            // stage this k-half of B
            #pragma unroll
            for (int it = 0; it < 8; ++it) {
                int idx = tid + it * 256;            // 0..2047
                int k = idx >> 5, n4 = (idx & 31) << 2;
                float4 v = *(const float4*)&Ws[mat][(size_t)(kh * 64 + k) * CP + n4];
                uint4 u = make_uint4(f2tf32(v.x), f2tf32(v.y), f2tf32(v.z), f2tf32(v.w));
                *(uint4*)&Bs[k * PB_STRIDE + n4] = u;
            }
            __syncthreads();

            #pragma unroll
            for (int ks = 0; ks < 8; ++ks) {
                const int k0 = ks * 8;
                const int ka = kh * 64 + k0;
                uint32_t a[2][4], b[4][2];
                #pragma unroll
                for (int mf = 0; mf < 2; ++mf) {
                    int r = warp_m * 32 + mf * 16 + gid;
                    a[mf][0] = As[r * PA_STRIDE + ka + tig];
                    a[mf][1] = As[(r + 8) * PA_STRIDE + ka + tig];
                    a[mf][2] = As[r * PA_STRIDE + ka + tig + 4];
                    a[mf][3] = As[(r + 8) * PA_STRIDE + ka + tig + 4];
                }
                #pragma unroll
                for (int nf = 0; nf < 4; ++nf) {
                    int n = warp_n * 32 + nf * 8 + gid;
                    b[nf][0] = Bs[(k0 + tig) * PB_STRIDE + n];
                    b[nf][1] = Bs[(k0 + tig + 4) * PB_STRIDE + n];
                }
                #pragma unroll
                for (int mf = 0; mf < 2; ++mf)
                    #pragma unroll
                    for (int nf = 0; nf < 4; ++nf)
                        mma_tf32(c[mf][nf], a[mf][0], a[mf][1], a[mf][2], a[mf][3],
                                 b[nf][0], b[nf][1]);
            }
            __syncthreads();
        }

        float* O = Os[mat];
        #pragma unroll
        for (int mf = 0; mf < 2; ++mf) {
            #pragma unroll
            for (int nf = 0; nf < 4; ++nf) {
                int r  = m0 + warp_m * 32 + mf * 16 + gid;
                int cb = warp_n * 32 + nf * 8 + 2 * tig;
                float v0 = c[mf][nf][0], v1 = c[mf][nf][1];
                float v2 = c[mf][nf][2], v3 = c[mf][nf][3];
                if (mat == 3) {
                    v0 = 1.f / (1.f + __expf(-v0));
                    v1 = 1.f / (1.f + __expf(-v1));
                    v2 = 1.f / (1.f + __expf(-v2));
                    v3 = 1.f / (1.f + __expf(-v3));
                }
                *(float2*)&O[(size_t)r * CP + cb]       = make_float2(v0, v1);
                *(float2*)&O[(size_t)(r + 8) * CP + cb] = make_float2(v2, v3);
            }
        }
    }
}

// ----------------------------------------------- output projection (tf32 mma)
__global__ void __launch_bounds__(256, 3) k_out_mma(const float* __restrict__ Wout,
                                                    float* __restrict__ out)
{
    extern __shared__ uint32_t usm[];
    uint32_t* As = usm;
    uint32_t* Bs = usm + 64 * PA_STRIDE;

    const int tid = threadIdx.x;
    const int wid = tid >> 5, lane = tid & 31;
    const int warp_m = wid & 1, warp_n = wid >> 1;
    const int gid = lane >> 2, tig = lane & 3;
    const int m0 = blockIdx.x * 64;

    #pragma unroll
    for (int it = 0; it < 8; ++it) {
        int idx = tid + it * 256;
        int r = idx >> 5, c4 = (idx & 31) << 2;
        float4 v = *(const float4*)&g_o[(size_t)(m0 + r) * CP + c4];
        uint4 u = make_uint4(f2tf32(v.x), f2tf32(v.y), f2tf32(v.z), f2tf32(v.w));
        *(uint4*)&As[r * PA_STRIDE + c4] = u;
    }

    float c[2][4][4];
    #pragma unroll
    for (int mf = 0; mf < 2; ++mf)
        #pragma unroll
        for (int nf = 0; nf < 4; ++nf)
            #pragma unroll
            for (int q = 0; q < 4; ++q) c[mf][nf][q] = 0.f;

    #pragma unroll
    for (int kh = 0; kh < 2; ++kh) {
        #pragma unroll
        for (int it = 0; it < 8; ++it) {
            int idx = tid + it * 256;
            int k = idx >> 5, n4 = (idx & 31) << 2;
            float4 v = *(const float4*)&Wout[(size_t)(kh * 64 + k) * CP + n4];
            uint4 u = make_uint4(f2tf32(v.x), f2tf32(v.y), f2tf32(v.z), f2tf32(v.w));
            *(uint4*)&Bs[k * PB_STRIDE + n4] = u;
        }
        __syncthreads();

        #pragma unroll
        for (int ks = 0; ks < 8; ++ks) {
            const int k0 = ks * 8;
            const int ka = kh * 64 + k0;
            uint32_t a[2][4], b[4][2];
            #pragma unroll
            for (int mf = 0; mf < 2; ++mf) {
                int r = warp_m * 32 + mf * 16 + gid;
                a[mf][0] = As[r * PA_STRIDE + ka + tig];
                a[mf][1] = As[(r + 8) * PA_STRIDE + ka + tig];
                a[mf][2] = As[r * PA_STRIDE + ka + tig + 4];
                a[mf][3] = As[(r + 8) * PA_STRIDE + ka + tig + 4];
            }
            #pragma unroll
            for (int nf = 0; nf < 4; ++nf) {
                int n = warp_n * 32 + nf * 8 + gid;
                b[nf][0] = Bs[(k0 + tig) * PB_STRIDE + n];
                b[nf][1] = Bs[(k0 + tig + 4) * PB_STRIDE + n];
            }
            #pragma unroll
            for (int mf = 0; mf < 2; ++mf)
                #pragma unroll
                for (int nf = 0; nf < 4; ++nf)
                    mma_tf32(c[mf][nf], a[mf][0], a[mf][1], a[mf][2], a[mf][3],
                             b[nf][0], b[nf][1]);
        }
        __syncthreads();
    }

    #pragma unroll
    for (int mf = 0; mf < 2; ++mf) {
        #pragma unroll
        for (int nf = 0; nf < 4; ++nf) {
            int r  = m0 + warp_m * 32 + mf * 16 + gid;
            int cb = warp_n * 32 + nf * 8 + 2 * tig;
            *(float2*)&out[(size_t)r * CP + cb] =
                make_float2(c[mf][nf][0], c[mf][nf][1]);
            *(float2*)&out[(size_t)(r + 8) * CP + cb] =
                make_float2(c[mf][nf][2], c[mf][nf][3]);
        }
    }
}

// ------------------------------------------------ attention (tf32 mma.sync)
// One CTA per (i,h), 256 threads = 8 warps, 8 j-tiles of 32, 2 CTAs/SM.
// PV: warp = m16 x n8 tile, full K=256 per warp (no partial reduction).
#define KC_S 264
#define V_S  40
#define Q_S  40
#define P_S  264
#define JT   32
#define OFF_KC 0
#define OFF_V  (32 * KC_S)
#define OFF_Q  (OFF_V + 256 * V_S)
#define OFF_P  (OFF_Q + JT * Q_S)
#define OFF_INV (OFF_P + JT * P_S)
#define ATTN_WORDS (OFF_INV + JT)
#define ATTN_SMEM (ATTN_WORDS * 4)

__global__ void __launch_bounds__(256, 2) k_attn_mma()
{
    extern __shared__ uint32_t usm[];
    uint32_t* Kc  = usm + OFF_KC;   // [32][264] tf32, c-major K
    uint32_t* Vs  = usm + OFF_V;    // [256][40] tf32
    uint32_t* Qs  = usm + OFF_Q;    // [32][40]  tf32 (pre-scaled)
    uint32_t* Ps  = usm + OFF_P;    // [32][264] logits -> exp(tf32); temp K at start
    float*    invs = (float*)(usm + OFF_INV);

    const int i = blockIdx.x, h = blockIdx.y;
    const int tid = threadIdx.x;
    const int wid = tid >> 5, lane = tid & 31;
    const int gid = lane >> 2, tig = lane & 3;
    const float scale = 0.17677669529663687f;  // 1/sqrt(32)

    const float* gk = g_k + (size_t)(i * 256) * CP + h * 32;
    const float* gv = g_v + (size_t)(i * 256) * CP + h * 32;
    const float* gq = g_q + (size_t)(i * 256) * CP + h * 32;
    const float* gg = g_g + (size_t)(i * 256) * CP + h * 32;
    const float* __restrict__ gb = g_b + (size_t)h * NN;

    // stage 1: K natural (tf32) into Ps temp [256][33] (conflict-free), V natural
    #pragma unroll
    for (int it = 0; it < 8; ++it) {
        int idx = tid + it * 256;
        int kk = idx >> 3, c4 = (idx & 7) << 2;
        float4 kv = *(const float4*)&gk[kk * CP + c4];
        Ps[kk * 33 + c4 + 0] = f2tf32(kv.x);
        Ps[kk * 33 + c4 + 1] = f2tf32(kv.y);
        Ps[kk * 33 + c4 + 2] = f2tf32(kv.z);
        Ps[kk * 33 + c4 + 3] = f2tf32(kv.w);
        float4 vv = *(const float4*)&gv[kk * CP + c4];
        *(uint4*)&Vs[kk * V_S + c4] =
            make_uint4(f2tf32(vv.x), f2tf32(vv.y), f2tf32(vv.z), f2tf32(vv.w));
    }
    __syncthreads();

    // stage 2: smem transpose -> Kc[c][key] (all phases conflict-free)
    #pragma unroll
    for (int c = 0; c < 32; ++c)
        Kc[c * KC_S + tid] = Ps[tid * 33 + c];
    __syncthreads();

    for (int jt = 0; jt < 8; ++jt) {
        const int j0 = jt * JT;

        // stage Q tile (scaled, tf32): 32 rows x 8 float4
        {
            int r = tid >> 3, c4 = (tid & 7) << 2;
            float4 q = *(const float4*)&gq[(j0 + r) * CP + c4];
            *(uint4*)&Qs[r * Q_S + c4] =
                make_uint4(f2tf32(q.x * scale), f2tf32(q.y * scale),
                           f2tf32(q.z * scale), f2tf32(q.w * scale));
        }
        __syncthreads();

        // ---- S = Q K^T : warp wid covers cols wid*32..+31, rows 0..31 ----
        {
            float c[2][4][4];
            #pragma unroll
            for (int mf = 0; mf < 2; ++mf)
                #pragma unroll
                for (int nf = 0; nf < 4; ++nf)
                    #pragma unroll
                    for (int q = 0; q < 4; ++q) c[mf][nf][q] = 0.f;

            #pragma unroll
            for (int ks = 0; ks < 4; ++ks) {
                const int c0 = ks * 8;
                uint32_t a[2][4], b[4][2];
                #pragma unroll
                for (int mf = 0; mf < 2; ++mf) {
                    int r = mf * 16 + gid;
                    a[mf][0] = Qs[r * Q_S + c0 + tig];
                    a[mf][1] = Qs[(r + 8) * Q_S + c0 + tig];
                    a[mf][2] = Qs[r * Q_S + c0 + tig + 4];
                    a[mf][3] = Qs[(r + 8) * Q_S + c0 + tig + 4];
                }
                #pragma unroll
                for (int nf = 0; nf < 4; ++nf) {
                    int n = wid * 32 + nf * 8 + gid;
                    b[nf][0] = Kc[(c0 + tig) * KC_S + n];
                    b[nf][1] = Kc[(c0 + tig + 4) * KC_S + n];
                }
                #pragma unroll
                for (int mf = 0; mf < 2; ++mf)
                    #pragma unroll
                    for (int nf = 0; nf < 4; ++nf)
                        mma_tf32(c[mf][nf], a[mf][0], a[mf][1], a[mf][2], a[mf][3],
                                 b[nf][0], b[nf][1]);
            }

            #pragma unroll
            for (int mf = 0; mf < 2; ++mf)
                #pragma unroll
                for (int nf = 0; nf < 4; ++nf) {
                    int r  = mf * 16 + gid;
                    int cb = wid * 32 + nf * 8 + 2 * tig;
                    *(float2*)&Ps[r * P_S + cb] =
                        make_float2(c[mf][nf][0], c[mf][nf][1]);
                    *(float2*)&Ps[(r + 8) * P_S + cb] =
                        make_float2(c[mf][nf][2], c[mf][nf][3]);
                }
        }
        __syncthreads();

        // ---- SIMT softmax: warp owns rows wid*4..+3 (full 256 cols) ----
        #pragma unroll
        for (int rr = 0; rr < 4; ++rr) {
            const int r = wid * 4 + rr;
            const int jglob = j0 + r;
            float v[8];
            #pragma unroll
            for (int u = 0; u < 8; ++u)
                v[u] = __uint_as_float(Ps[r * P_S + lane + 32 * u])
                     + __ldg(&gb[jglob * 256 + lane + 32 * u]);
            float m = v[0];
            #pragma unroll
            for (int u = 1; u < 8; ++u) m = fmaxf(m, v[u]);
            #pragma unroll
            for (int off = 16; off; off >>= 1)
                m = fmaxf(m, __shfl_xor_sync(0xffffffffu, m, off));
            float s = 0.f;
            #pragma unroll
            for (int u = 0; u < 8; ++u) {
                uint32_t uq = f2tf32(__expf(v[u] - m));
                Ps[r * P_S + lane + 32 * u] = uq;
                s += __uint_as_float(uq);
            }
            #pragma unroll
            for (int off = 16; off; off >>= 1)
                s += __shfl_xor_sync(0xffffffffu, s, off);
            if (lane == 0) invs[r] = 1.f / s;
        }
        __syncthreads();

        // ---- O = P V : warp (wm = wid&1 -> 16 rows, wn = wid>>1 -> 8 cols),
        //      full K=256, two interleaved accumulator chains ----
        {
            const int wm = wid & 1, wn = wid >> 1;
            float oa[4] = {0.f, 0.f, 0.f, 0.f};
            float ob[4] = {0.f, 0.f, 0.f, 0.f};
            const int r0 = wm * 16 + gid;
            const int nb = wn * 8 + gid;

            #pragma unroll
            for (int ks = 0; ks < 32; ks += 2) {
                const int k0 = ks * 8;
                uint32_t a0 = Ps[r0 * P_S + k0 + tig];
                uint32_t a1 = Ps[(r0 + 8) * P_S + k0 + tig];
                uint32_t a2 = Ps[r0 * P_S + k0 + tig + 4];
                uint32_t a3 = Ps[(r0 + 8) * P_S + k0 + tig + 4];
                uint32_t b0 = Vs[(k0 + tig) * V_S + nb];
                uint32_t b1 = Vs[(k0 + tig + 4) * V_S + nb];
                mma_tf32(oa, a0, a1, a2, a3, b0, b1);

                const int k1 = k0 + 8;
                uint32_t c0r = Ps[r0 * P_S + k1 + tig];
                uint32_t c1r = Ps[(r0 + 8) * P_S + k1 + tig];
                uint32_t c2r = Ps[r0 * P_S + k1 + tig + 4];
                uint32_t c3r = Ps[(r0 + 8) * P_S + k1 + tig + 4];
                uint32_t d0 = Vs[(k1 + tig) * V_S + nb];
                uint32_t d1 = Vs[(k1 + tig + 4) * V_S + nb];
                mma_tf32(ob, c0r, c1r, c2r, c3r, d0, d1);
            }

            // epilogue: 1/sum + gate, direct gmem write
            const int r1 = r0 + 8;
            const int cc = wn * 8 + 2 * tig;
            float i0 = invs[r0], i1 = invs[r1];
            float2 g0 = *(const float2*)&gg[(j0 + r0) * CP + cc];
            float2 g1 = *(const float2*)&gg[(j0 + r1) * CP + cc];
            float2 w0 = make_float2((oa[0] + ob[0]) * i0 * g0.x,
                                    (oa[1] + ob[1]) * i0 * g0.y);
            float2 w1 = make_float2((oa[2] + ob[2]) * i1 * g1.x,
                                    (oa[3] + ob[3]) * i1 * g1.y);
            *(float2*)&g_o[(size_t)(i * 256 + j0 + r0) * CP + h * 32 + cc] = w0;
            *(float2*)&g_o[(size_t)(i * 256 + j0 + r1) * CP + h * 32 + cc] = w1;
        }
        __syncthreads();
    }
}

// ----------------------------------------------------------------- launcher
extern "C" void kernel_launch(void* const* d_in, const int* in_sizes, int n_in,
                              void* d_out, int out_size)
{
    const float* pair  = (const float*)d_in[0];
    const float* gamma = (const float*)d_in[1];
    const float* beta  = (const float*)d_in[2];
    const float* Wq    = (const float*)d_in[3];
    const float* Wk    = (const float*)d_in[4];
    const float* Wv    = (const float*)d_in[5];
    const float* Wb    = (const float*)d_in[6];
    const float* Wg    = (const float*)d_in[7];
    const float* Wout  = (const float*)d_in[8];
    float* out = (float*)d_out;

    cudaFuncSetAttribute(k_proj_mma, cudaFuncAttributeMaxDynamicSharedMemorySize, PJ_SMEM);
    cudaFuncSetAttribute(k_out_mma,  cudaFuncAttributeMaxDynamicSharedMemorySize, PJ_SMEM);
    cudaFuncSetAttribute(k_attn_mma, cudaFuncAttributeMaxDynamicSharedMemorySize, ATTN_SMEM);

    k_ln      <<<NN / 8, 256>>>(pair, gamma, beta, Wb);
    k_proj_mma<<<NN / 64, 256, PJ_SMEM>>>(Wq, Wk, Wv, Wg);
    k_attn_mma<<<dim3(N_TOKEN, H), 256, ATTN_SMEM>>>();
    k_out_mma <<<NN / 64, 256, PJ_SMEM>>>(Wout, out);
}